// round 10
// baseline (speedup 1.0000x reference)
#include <cuda_runtime.h>
#include <cuda_bf16.h>
#include <cstdint>

// Problem shape constants (fixed by the reference).
#define BB 2
#define LL 2048
#define DD 1024
#define HH 16
#define HD 64
#define ROWS (BB*LL)            // 4096
#define QKV_N (3*DD)            // 3072
#define BLD (BB*LL*DD)          // 4194304
#define WQKV_SZ (QKV_N*DD)      // 3145728
#define WOUT_SZ (DD*DD)         // 1048576

// ---------------------------------------------------------------------------
// Scratch (alloc-free rule: __device__ globals)
// ---------------------------------------------------------------------------
__device__ float g_xr  [BLD];
__device__ float g_wqkv[WQKV_SZ];
__device__ float g_wout[WOUT_SZ];
__device__ float g_qkv [ROWS * QKV_N];
__device__ float g_q   [BLD];
__device__ float g_k   [BLD];
__device__ float g_v   [BLD];
__device__ float g_ctx [BLD];

// ---------------------------------------------------------------------------
// Helpers
// ---------------------------------------------------------------------------
__device__ __forceinline__ uint32_t f2tf(float f) {
    uint32_t r;
    asm("cvt.rna.tf32.f32 %0, %1;" : "=r"(r) : "f"(f));
    return r;
}

__device__ __forceinline__ uint32_t smem_u32(const void* p) {
    uint32_t a;
    asm("{ .reg .u64 t; cvta.to.shared.u64 t, %1; cvt.u32.u64 %0, t; }"
        : "=r"(a) : "l"(p));
    return a;
}

// m16n8k8 tf32 mma (.row.col)
__device__ __forceinline__ void mma8(float* c, const uint32_t* a, const uint32_t* b) {
    asm volatile(
        "mma.sync.aligned.m16n8k8.row.col.f32.tf32.tf32.f32 "
        "{%0,%1,%2,%3}, {%4,%5,%6,%7}, {%8,%9}, {%0,%1,%2,%3};"
        : "+f"(c[0]), "+f"(c[1]), "+f"(c[2]), "+f"(c[3])
        : "r"(a[0]), "r"(a[1]), "r"(a[2]), "r"(a[3]), "r"(b[0]), "r"(b[1]));
}

// ldmatrix x4 (b32 data viewed as b16 pairs; mapping matches mma frags)
__device__ __forceinline__ void ldsm4(uint32_t* r, uint32_t addr) {
    asm volatile(
        "ldmatrix.sync.aligned.m8n8.x4.shared.b16 {%0,%1,%2,%3}, [%4];"
        : "=r"(r[0]), "=r"(r[1]), "=r"(r[2]), "=r"(r[3]) : "r"(addr));
}

#define CP16(dst, src) \
    asm volatile("cp.async.cg.shared.global [%0], [%1], 16;" :: "r"(dst), "l"(src))
#define CP_COMMIT() asm volatile("cp.async.commit_group;" ::: "memory")
#define CP_WAIT(n)  asm volatile("cp.async.wait_group %0;" :: "n"(n) : "memory")

// ---------------------------------------------------------------------------
// Fused round-to-tf32 of x, Wqkv, Wout
// ---------------------------------------------------------------------------
#define RND_TOTAL4 ((BLD + WQKV_SZ + WOUT_SZ) / 4)

__global__ __launch_bounds__(256) void round_all(
    const float4* __restrict__ x,   float4* __restrict__ xr,
    const float4* __restrict__ wq,  float4* __restrict__ wqr,
    const float4* __restrict__ wo,  float4* __restrict__ wor)
{
    int i = blockIdx.x * 256 + threadIdx.x;
    if (i >= RND_TOTAL4) return;
    const float4* src; float4* dst;
    if (i < BLD/4)                       { src = x;  dst = xr;  }
    else if (i < (BLD + WQKV_SZ)/4)      { src = wq; dst = wqr; i -= BLD/4; }
    else                                 { src = wo; dst = wor; i -= (BLD + WQKV_SZ)/4; }
    float4 v = src[i];
    float4 o;
    o.x = __uint_as_float(f2tf(v.x));
    o.y = __uint_as_float(f2tf(v.y));
    o.z = __uint_as_float(f2tf(v.z));
    o.w = __uint_as_float(f2tf(v.w));
    dst[i] = o;
}

// ---------------------------------------------------------------------------
// tf32 mma.sync NT GEMM (unchanged): 128x128 CTA tile, BK=32, 256 threads,
// ldmatrix fragments, smem stride 36.
// ---------------------------------------------------------------------------
#define GSTR 36
#define GEMM_SMEM (2 * 2 * 128 * GSTR * 4)

__global__ __launch_bounds__(256) void gemm_mma(
    const float* __restrict__ A, const float* __restrict__ B,
    const float* __restrict__ bias, float* __restrict__ C,
    int N, int K)
{
    extern __shared__ float sm[];
    float* As = sm;
    float* Bs = sm + 2 * 128 * GSTR;
    const uint32_t As_u = smem_u32(As);
    const uint32_t Bs_u = smem_u32(Bs);

    const int tid  = threadIdx.x;
    const int lane = tid & 31;
    const int wid  = tid >> 5;
    const int wm   = wid & 1;
    const int wn   = wid >> 1;
    const int lq   = lane >> 2;
    const int ls   = lane & 3;
    const int s    = lane >> 3;
    const int srow = lane & 7;

    const uint32_t a_lane =
        (uint32_t)(((wm * 64) + (s & 1) * 8 + srow) * GSTR + (s >> 1) * 4) * 4;
    const uint32_t b_lane =
        (uint32_t)(((wn * 32) + (s >> 1) * 8 + srow) * GSTR + (s & 1) * 4) * 4;

    const float* Ab = A + (size_t)(blockIdx.y * 128) * K;
    const float* Bb = B + (size_t)(blockIdx.x * 128) * K;
    const int KS = K >> 5;

    float acc[4][4][4];
#pragma unroll
    for (int mt = 0; mt < 4; ++mt)
#pragma unroll
        for (int nt = 0; nt < 4; ++nt)
#pragma unroll
            for (int r = 0; r < 4; ++r) acc[mt][nt][r] = 0.f;

#define GEMM_LOAD(ks, db)                                                     \
    {                                                                         \
        const int k0 = (ks) * 32;                                             \
        const uint32_t dA = As_u + (db) * 128 * GSTR * 4;                     \
        const uint32_t dB = Bs_u + (db) * 128 * GSTR * 4;                     \
        _Pragma("unroll")                                                     \
        for (int i = 0; i < 4; ++i) {                                         \
            const int c   = tid + i * 256;                                    \
            const int row = c >> 3;                                           \
            const int cc  = (c & 7) * 4;                                      \
            const uint32_t off = (uint32_t)(row * GSTR + cc) * 4;             \
            CP16(dA + off, Ab + (size_t)row * K + k0 + cc);                   \
            CP16(dB + off, Bb + (size_t)row * K + k0 + cc);                   \
        }                                                                     \
        CP_COMMIT();                                                          \
    }

    GEMM_LOAD(0, 0);

    for (int ks = 0; ks < KS; ++ks) {
        const int db = ks & 1;
        if (ks + 1 < KS) { GEMM_LOAD(ks + 1, db ^ 1); CP_WAIT(1); }
        else             { CP_WAIT(0); }
        __syncthreads();

        const uint32_t Ad_u = As_u + db * 128 * GSTR * 4;
        const uint32_t Bd_u = Bs_u + db * 128 * GSTR * 4;

#pragma unroll
        for (int kb = 0; kb < 4; ++kb) {
            uint32_t a[4][4], b[2][4];
#pragma unroll
            for (int mt = 0; mt < 4; ++mt)
                ldsm4(a[mt], Ad_u + a_lane + (uint32_t)(mt * 16 * GSTR + kb * 8) * 4);
#pragma unroll
            for (int ntp = 0; ntp < 2; ++ntp)
                ldsm4(b[ntp], Bd_u + b_lane + (uint32_t)(ntp * 16 * GSTR + kb * 8) * 4);
#pragma unroll
            for (int mt = 0; mt < 4; ++mt)
#pragma unroll
                for (int nt = 0; nt < 4; ++nt)
                    mma8(acc[mt][nt], a[mt], &b[nt >> 1][(nt & 1) * 2]);
        }
        __syncthreads();
    }

    const int row_base = blockIdx.y * 128 + wm * 64;
    const int col_base = blockIdx.x * 128 + wn * 32;
#pragma unroll
    for (int mt = 0; mt < 4; ++mt) {
        const int r0 = row_base + mt * 16 + lq;
#pragma unroll
        for (int nt = 0; nt < 4; ++nt) {
            const int cn = col_base + nt * 8 + ls * 2;
            const float2 bb = *(const float2*)(bias + cn);
            float2 o0, o1;
            o0.x = acc[mt][nt][0] + bb.x;  o0.y = acc[mt][nt][1] + bb.y;
            o1.x = acc[mt][nt][2] + bb.x;  o1.y = acc[mt][nt][3] + bb.y;
            *(float2*)(C + (size_t)r0 * N + cn)       = o0;
            *(float2*)(C + (size_t)(r0 + 8) * N + cn) = o1;
        }
    }
}

// ---------------------------------------------------------------------------
// RoPE + head scatter (unchanged).
// ---------------------------------------------------------------------------
__global__ __launch_bounds__(256) void rope_scatter(
    const float* __restrict__ qkv,
    float* __restrict__ qh, float* __restrict__ kh, float* __restrict__ vh,
    float* __restrict__ kout, float* __restrict__ vout)
{
    const int t = blockIdx.x * blockDim.x + threadIdx.x;
    const int d = t & 31;
    const int h = (t >> 5) & 15;
    const int l = (t >> 9) & 2047;
    const int b = t >> 20;

    const float* base = qkv + (size_t)(b * LL + l) * QKV_N;

    const float inv = __expf(-(float)d * (9.210340371976184f / 32.f));
    const float ang = (float)l * inv;
    float sn, cs;
    sincosf(ang, &sn, &cs);

    const size_t ob = ((size_t)((b * HH + h) * LL + l)) * HD;

    const float q1 = base[h*HD + d], q2 = base[h*HD + d + 32];
    qh[ob + d]      = __uint_as_float(f2tf((q1 * cs - q2 * sn) * 0.125f));
    qh[ob + d + 32] = __uint_as_float(f2tf((q1 * sn + q2 * cs) * 0.125f));

    const float k1 = base[DD + h*HD + d], k2 = base[DD + h*HD + d + 32];
    const float kr1 = k1 * cs - k2 * sn;
    const float kr2 = k1 * sn + k2 * cs;
    kout[ob + d]      = kr1;
    kout[ob + d + 32] = kr2;
    kh[ob + d]        = __uint_as_float(f2tf(kr1));
    kh[ob + d + 32]   = __uint_as_float(f2tf(kr2));

    const float v1 = base[2*DD + h*HD + d], v2 = base[2*DD + h*HD + d + 32];
    vout[ob + d]      = v1;
    vout[ob + d + 32] = v2;
    vh[ob + d]        = __uint_as_float(f2tf(v1));
    vh[ob + d + 32]   = __uint_as_float(f2tf(v2));
}

// ---------------------------------------------------------------------------
// Flash attention v7: Br=64, Bc=64, 128 threads (4 warps = 2 row x 2 col),
// 3 CTAs/SM (launch_bounds-forced). 32-row warps; Q dims 0-31 in registers,
// dims 32-63 ldsm'd from a small smem tile. K single-buffered via cp.async;
// V loaded LDG->STS (transposed) each iter. Per-warp online softmax over its
// 32-token column group; 2-way split-KV combine in the epilogue.
// smem (floats): Ks[64*68] | Vt[64*68] | Qs[64*36] | Ps[4*32*36] | cm[128] |
// cl[128]; epilogue 'ac' (64 x 66) aliases Ks.  Total 63488 B.
// ---------------------------------------------------------------------------
#define FSTR 68
#define PSTR 36
#define FVT_OFF (64*FSTR)                   // 4352
#define FQS_OFF (FVT_OFF + 64*FSTR)         // 8704
#define FPS_OFF (FQS_OFF + 64*PSTR)         // 11008
#define FCM_OFF (FPS_OFF + 4*32*PSTR)       // 15616
#define FCL_OFF (FCM_OFF + 128)             // 15744
#define FLASH_SMEM ((FCL_OFF + 128) * 4)    // 63488 B

__global__ void __launch_bounds__(128, 3) flash_mma(
    const float* __restrict__ Q, const float* __restrict__ K,
    const float* __restrict__ V, float* __restrict__ ctx)
{
    extern __shared__ float sm[];
    float* Ks = sm;
    float* Vt = sm + FVT_OFF;
    float* Ps = sm + FPS_OFF;
    float* cm = sm + FCM_OFF;
    float* cl = sm + FCL_OFF;
    float* ac = sm;                      // epilogue alias of Ks, stride 66
    const uint32_t Ks_u = smem_u32(Ks);
    const uint32_t Vt_u = smem_u32(Vt);
    const uint32_t Qs_u = smem_u32(sm + FQS_OFF);
    const uint32_t Ps_u = smem_u32(Ps);

    const int qi   = gridDim.x - 1 - blockIdx.x;   // heavy tiles first
    const int bh   = blockIdx.y;
    const int tid  = threadIdx.x;
    const int lane = tid & 31;
    const int wid  = tid >> 5;           // 0..3
    const int wr   = wid & 1;            // row group (2 x 32 rows)
    const int wc   = wid >> 1;           // col group (2 x 32 tokens)
    const int lq   = lane >> 2;
    const int ls   = lane & 3;
    const int s    = lane >> 3;
    const int srow = lane & 7;
    const int row0 = wr * 32;            // warp's first row (0 or 32)

    // ldmatrix lane offsets (bytes)
    const uint32_t bk_lane =
        (uint32_t)(((s >> 1) * 8 + srow) * FSTR + (s & 1) * 4) * 4;
    const uint32_t ap_lane =
        (uint32_t)(((s & 1) * 8 + srow) * PSTR + (s >> 1) * 4) * 4;
    const uint32_t Psw_u = Ps_u + (uint32_t)(wid * 32 * PSTR) * 4;
    float* Psw = Ps + wid * 32 * PSTR;

    const float* Qb = Q + ((size_t)bh * LL + qi * 64) * HD;
    const float* Kb = K + (size_t)bh * LL * HD;
    const float* Vb = V + (size_t)bh * LL * HD;

    // K tile loader: 64x64 floats, 128 threads -> 8 cp.async each
#define FL_LOAD_K(src)                                                        \
    {                                                                         \
        _Pragma("unroll")                                                     \
        for (int i = 0; i < 8; ++i) {                                         \
            const int c   = tid + i * 128;                                    \
            const int row = c >> 4;                                           \
            const int cc  = (c & 15) * 4;                                     \
            CP16(Ks_u + (uint32_t)(row * FSTR + cc) * 4,                      \
                 (src) + (size_t)row * HD + cc);                              \
        }                                                                     \
    }

    const int vtok = tid & 63;           // token within tile
    const int vseg = tid >> 6;           // 0/1 -> 32 dims each

    // prologue: K0 + Q-half (dims 32..63) in one cp.async group
    FL_LOAD_K(Kb);
#pragma unroll
    for (int i = 0; i < 4; ++i) {
        const int c   = tid + i * 128;
        const int row = c >> 3;
        const int cc  = (c & 7) * 4;
        CP16(Qs_u + (uint32_t)(row * PSTR + cc) * 4,
             Qb + (size_t)row * HD + 32 + cc);
    }
    CP_COMMIT();

    // Q dims 0..31 register-resident
    uint32_t qf[4][2][4];
#pragma unroll
    for (int kb = 0; kb < 4; ++kb) {
        const int k = kb * 8 + ls;
#pragma unroll
        for (int mt = 0; mt < 2; ++mt) {
            const int r = row0 + mt * 16 + lq;
            qf[kb][mt][0] = __float_as_uint(Qb[(size_t)r * HD + k]);
            qf[kb][mt][1] = __float_as_uint(Qb[(size_t)(r + 8) * HD + k]);
            qf[kb][mt][2] = __float_as_uint(Qb[(size_t)r * HD + k + 4]);
            qf[kb][mt][3] = __float_as_uint(Qb[(size_t)(r + 8) * HD + k + 4]);
        }
    }

    float acc[2][8][4];
#pragma unroll
    for (int mt = 0; mt < 2; ++mt)
#pragma unroll
        for (int nt = 0; nt < 8; ++nt)
#pragma unroll
            for (int r = 0; r < 4; ++r) acc[mt][nt][r] = 0.f;
    float mm[4] = {-1e30f, -1e30f, -1e30f, -1e30f};
    float llv[4] = {0.f, 0.f, 0.f, 0.f};

    for (int jt = 0; jt <= qi; ++jt) {
        if (jt > 0) {
            __syncthreads();             // drain reads of K_{jt-1}, V_{jt-1}
            FL_LOAD_K(Kb + (size_t)jt * 64 * HD);
            CP_COMMIT();
        }
        // V fill (LDG -> transposed STS), 8-float chunks to bound transients
        {
            const float* vb = Vb + ((size_t)jt * 64 + vtok) * HD + vseg * 32;
#pragma unroll
            for (int g = 0; g < 4; ++g) {
                float4 a = *(const float4*)(vb + g * 8);
                float4 b = *(const float4*)(vb + g * 8 + 4);
                const int d0 = vseg * 32 + g * 8;
                Vt[(d0 + 0) * FSTR + vtok] = a.x;
                Vt[(d0 + 1) * FSTR + vtok] = a.y;
                Vt[(d0 + 2) * FSTR + vtok] = a.z;
                Vt[(d0 + 3) * FSTR + vtok] = a.w;
                Vt[(d0 + 4) * FSTR + vtok] = b.x;
                Vt[(d0 + 5) * FSTR + vtok] = b.y;
                Vt[(d0 + 6) * FSTR + vtok] = b.z;
                Vt[(d0 + 7) * FSTR + vtok] = b.w;
            }
        }
        CP_WAIT(0);
        __syncthreads();                 // publish K_jt (+Qs on jt=0) and V_jt

        // ---- S = Q K^T on this warp's 32 tokens ----
        float sc[2][4][4];
#pragma unroll
        for (int mt = 0; mt < 2; ++mt)
#pragma unroll
            for (int nt = 0; nt < 4; ++nt)
#pragma unroll
                for (int r = 0; r < 4; ++r) sc[mt][nt][r] = 0.f;

        const uint32_t Kd_u = Ks_u + (uint32_t)(wc * 32 * FSTR) * 4 + bk_lane;
#pragma unroll
        for (int kb = 0; kb < 8; ++kb) {
            uint32_t at[2][4];
            if (kb >= 4) {
#pragma unroll
                for (int mt = 0; mt < 2; ++mt)
                    ldsm4(at[mt], Qs_u + ap_lane +
                          (uint32_t)((row0 + mt * 16) * PSTR + (kb - 4) * 8) * 4);
            } else {
#pragma unroll
                for (int mt = 0; mt < 2; ++mt)
#pragma unroll
                    for (int r = 0; r < 4; ++r) at[mt][r] = qf[kb][mt][r];
            }
#pragma unroll
            for (int ntp = 0; ntp < 2; ++ntp) {
                uint32_t b[4];
                ldsm4(b, Kd_u + (uint32_t)(ntp * 16 * FSTR + kb * 8) * 4);
#pragma unroll
                for (int mt = 0; mt < 2; ++mt) {
                    mma8(sc[mt][ntp * 2],     at[mt], b);
                    mma8(sc[mt][ntp * 2 + 1], at[mt], b + 2);
                }
            }
        }

        // ---- causal mask (diagonal tile only) ----
        if (jt == qi) {
            const int cbase = jt * 64 + wc * 32;
#pragma unroll
            for (int mt = 0; mt < 2; ++mt) {
                const int rg0 = qi * 64 + row0 + mt * 16 + lq;
#pragma unroll
                for (int nt = 0; nt < 4; ++nt) {
                    const int cg = cbase + nt * 8 + ls * 2;
                    if (cg > rg0)         sc[mt][nt][0] += -1000000000.0f;
                    if (cg + 1 > rg0)     sc[mt][nt][1] += -1000000000.0f;
                    if (cg > rg0 + 8)     sc[mt][nt][2] += -1000000000.0f;
                    if (cg + 1 > rg0 + 8) sc[mt][nt][3] += -1000000000.0f;
                }
            }
        }

        // ---- row max per row-pair group (quad shfl) ----
        float mx[4];
#pragma unroll
        for (int mt = 0; mt < 2; ++mt) {
            float a0 = sc[mt][0][0], a1 = sc[mt][0][2];
#pragma unroll
            for (int nt = 0; nt < 4; ++nt) {
                a0 = fmaxf(a0, fmaxf(sc[mt][nt][0], sc[mt][nt][1]));
                a1 = fmaxf(a1, fmaxf(sc[mt][nt][2], sc[mt][nt][3]));
            }
            mx[mt * 2]     = a0;
            mx[mt * 2 + 1] = a1;
        }
#pragma unroll
        for (int i = 0; i < 4; ++i) {
            mx[i] = fmaxf(mx[i], __shfl_xor_sync(0xffffffffu, mx[i], 1));
            mx[i] = fmaxf(mx[i], __shfl_xor_sync(0xffffffffu, mx[i], 2));
        }

        float al[4];
#pragma unroll
        for (int i = 0; i < 4; ++i) {
            const float mn = fmaxf(mm[i], mx[i]);
            al[i] = __expf(mm[i] - mn);
            mm[i] = mn;
        }

        // ---- P = exp(S - m), round, store to own Ps slice; row sums ----
        float rs[4] = {0.f, 0.f, 0.f, 0.f};
#pragma unroll
        for (int mt = 0; mt < 2; ++mt) {
            const float mn0 = mm[mt * 2], mn1 = mm[mt * 2 + 1];
#pragma unroll
            for (int nt = 0; nt < 4; ++nt) {
                const float p0 = __expf(sc[mt][nt][0] - mn0);
                const float p1 = __expf(sc[mt][nt][1] - mn0);
                const float p2 = __expf(sc[mt][nt][2] - mn1);
                const float p3 = __expf(sc[mt][nt][3] - mn1);
                rs[mt * 2]     += p0 + p1;
                rs[mt * 2 + 1] += p2 + p3;
                uint2 w0, w1;
                w0.x = f2tf(p0); w0.y = f2tf(p1);
                w1.x = f2tf(p2); w1.y = f2tf(p3);
                const int cc = nt * 8 + ls * 2;
                *(uint2*)(Psw + (mt * 16 + lq) * PSTR + cc)     = w0;
                *(uint2*)(Psw + (mt * 16 + lq + 8) * PSTR + cc) = w1;
            }
        }
#pragma unroll
        for (int i = 0; i < 4; ++i) {
            rs[i] += __shfl_xor_sync(0xffffffffu, rs[i], 1);
            rs[i] += __shfl_xor_sync(0xffffffffu, rs[i], 2);
            llv[i] = llv[i] * al[i] + rs[i];
        }

#pragma unroll
        for (int mt = 0; mt < 2; ++mt)
#pragma unroll
            for (int nt = 0; nt < 8; ++nt) {
                acc[mt][nt][0] *= al[mt * 2];     acc[mt][nt][1] *= al[mt * 2];
                acc[mt][nt][2] *= al[mt * 2 + 1]; acc[mt][nt][3] *= al[mt * 2 + 1];
            }
        __syncwarp();                    // Ps slice visible to own ldmatrix

        // ---- O += P V over this warp's 32 tokens, full 64 head dims ----
        const uint32_t Vd_u = Vt_u + bk_lane;
#pragma unroll
        for (int kb = 0; kb < 4; ++kb) {
            uint32_t a[2][4];
#pragma unroll
            for (int mt = 0; mt < 2; ++mt)
                ldsm4(a[mt], Psw_u + ap_lane +
                      (uint32_t)(mt * 16 * PSTR + kb * 8) * 4);
#pragma unroll
            for (int ntp = 0; ntp < 4; ++ntp) {
                uint32_t b[4];
                ldsm4(b, Vd_u +
                      (uint32_t)(ntp * 16 * FSTR + wc * 32 + kb * 8) * 4);
#pragma unroll
                for (int mt = 0; mt < 2; ++mt) {
                    mma8(acc[mt][ntp * 2],     a[mt], b);
                    mma8(acc[mt][ntp * 2 + 1], a[mt], b + 2);
                }
            }
        }
        __syncwarp();
    }

    // ---- epilogue: 2-way split-KV combine across the two column groups ----
    if (ls == 0) {
#pragma unroll
        for (int mt = 0; mt < 2; ++mt) {
            cm[wc * 64 + row0 + mt * 16 + lq]     = mm[mt * 2];
            cm[wc * 64 + row0 + mt * 16 + lq + 8] = mm[mt * 2 + 1];
            cl[wc * 64 + row0 + mt * 16 + lq]     = llv[mt * 2];
            cl[wc * 64 + row0 + mt * 16 + lq + 8] = llv[mt * 2 + 1];
        }
    }
    __syncthreads();                     // also fences all loop smem reads

    float sS[4], lt[4];
#pragma unroll
    for (int i = 0; i < 4; ++i) {
        const int row = row0 + (i >> 1) * 16 + (i & 1) * 8 + lq;
        const float mo = cm[(wc ^ 1) * 64 + row];
        const float lo = cl[(wc ^ 1) * 64 + row];
        const float M  = fmaxf(mm[i], mo);
        sS[i] = __expf(mm[i] - M);
        lt[i] = llv[i] * sS[i] + lo * __expf(mo - M);
    }

    if (wc == 1) {                       // publish scaled partial O
#pragma unroll
        for (int mt = 0; mt < 2; ++mt) {
            const int r = row0 + mt * 16 + lq;
#pragma unroll
            for (int nt = 0; nt < 8; ++nt) {
                const int cc = nt * 8 + ls * 2;
                float2 w0, w1;
                w0.x = acc[mt][nt][0] * sS[mt * 2];
                w0.y = acc[mt][nt][1] * sS[mt * 2];
                w1.x = acc[mt][nt][2] * sS[mt * 2 + 1];
                w1.y = acc[mt][nt][3] * sS[mt * 2 + 1];
                *(float2*)(ac + r * 66 + cc)       = w0;
                *(float2*)(ac + (r + 8) * 66 + cc) = w1;
            }
        }
    }
    __syncthreads();

    if (wc == 0) {
        const int b = bh >> 4;
        const int h = bh & 15;
#pragma unroll
        for (int mt = 0; mt < 2; ++mt) {
            const float inv0 = 1.f / lt[mt * 2];
            const float inv1 = 1.f / lt[mt * 2 + 1];
            const int r  = row0 + mt * 16 + lq;
            const int rg = qi * 64 + r;
#pragma unroll
            for (int nt = 0; nt < 8; ++nt) {
                const int cc = nt * 8 + ls * 2;
                const float2 p0 = *(const float2*)(ac + r * 66 + cc);
                const float2 p1 = *(const float2*)(ac + (r + 8) * 66 + cc);
                const int cn = h * HD + cc;
                uint2 o0, o1;
                o0.x = f2tf((acc[mt][nt][0] * sS[mt * 2] + p0.x) * inv0);
                o0.y = f2tf((acc[mt][nt][1] * sS[mt * 2] + p0.y) * inv0);
                o1.x = f2tf((acc[mt][nt][2] * sS[mt * 2 + 1] + p1.x) * inv1);
                o1.y = f2tf((acc[mt][nt][3] * sS[mt * 2 + 1] + p1.y) * inv1);
                *(uint2*)(ctx + (size_t)(b * LL + rg) * DD + cn)     = o0;
                *(uint2*)(ctx + (size_t)(b * LL + rg + 8) * DD + cn) = o1;
            }
        }
    }
}

// ---------------------------------------------------------------------------
// Launch
// ---------------------------------------------------------------------------
extern "C" void kernel_launch(void* const* d_in, const int* in_sizes, int n_in,
                              void* d_out, int out_size)
{
    const float* x       = (const float*)d_in[0];
    const float* Wqkv_w  = (const float*)d_in[2];
    const float* Wqkv_b  = (const float*)d_in[3];
    const float* Wout_w  = (const float*)d_in[4];
    const float* Wout_b  = (const float*)d_in[5];

    float* out  = (float*)d_out;
    float* kout = out + BLD;
    float* vout = kout + BLD;

    float *xr, *wqkv, *wout_r, *qkv, *qh, *kh, *vh, *ctx;
    cudaGetSymbolAddress((void**)&xr,     g_xr);
    cudaGetSymbolAddress((void**)&wqkv,   g_wqkv);
    cudaGetSymbolAddress((void**)&wout_r, g_wout);
    cudaGetSymbolAddress((void**)&qkv,    g_qkv);
    cudaGetSymbolAddress((void**)&qh,     g_q);
    cudaGetSymbolAddress((void**)&kh,     g_k);
    cudaGetSymbolAddress((void**)&vh,     g_v);
    cudaGetSymbolAddress((void**)&ctx,    g_ctx);

    cudaFuncSetAttribute(gemm_mma,
                         cudaFuncAttributeMaxDynamicSharedMemorySize, GEMM_SMEM);
    cudaFuncSetAttribute(flash_mma,
                         cudaFuncAttributeMaxDynamicSharedMemorySize, FLASH_SMEM);

    round_all<<<(RND_TOTAL4 + 255) / 256, 256>>>(
        (const float4*)x, (float4*)xr,
        (const float4*)Wqkv_w, (float4*)wqkv,
        (const float4*)Wout_w, (float4*)wout_r);

    gemm_mma<<<dim3(QKV_N / 128, ROWS / 128), 256, GEMM_SMEM>>>(
        xr, wqkv, Wqkv_b, qkv, QKV_N, DD);

    rope_scatter<<<(BB * LL * HH * 32) / 256, 256>>>(qkv, qh, kh, vh, kout, vout);

    flash_mma<<<dim3(LL / 64, BB * HH), 128, FLASH_SMEM>>>(qh, kh, vh, ctx);

    gemm_mma<<<dim3(DD / 128, ROWS / 128), 256, GEMM_SMEM>>>(
        ctx, wout_r, Wout_b, out, DD, DD);
}

// round 11
// speedup vs baseline: 1.6280x; 1.6280x over previous
#include <cuda_runtime.h>
#include <cuda_fp16.h>
#include <cstdint>

// Problem shape constants (fixed by the reference).
#define BB 2
#define LL 2048
#define DD 1024
#define HH 16
#define HD 64
#define ROWS (BB*LL)            // 4096
#define QKV_N (3*DD)            // 3072
#define BLD (BB*LL*DD)          // 4194304
#define WQKV_SZ (QKV_N*DD)      // 3145728
#define WOUT_SZ (DD*DD)         // 1048576

// ---------------------------------------------------------------------------
// Scratch (alloc-free rule: __device__ globals)
// ---------------------------------------------------------------------------
__device__ __half g_xr  [BLD];            // x -> fp16
__device__ __half g_wqkv[WQKV_SZ];        // Wqkv -> fp16
__device__ __half g_wout[WOUT_SZ];        // Wout -> fp16
__device__ float  g_qkv [ROWS * QKV_N];   // qkv projection (fp32 accum)
__device__ __half g_q   [BLD];            // q heads, rope'd, scaled, fp16
__device__ __half g_k   [BLD];            // k heads, rope'd, fp16
__device__ __half g_v   [BLD];            // v heads, fp16
__device__ __half g_ctx [BLD];            // attention context, fp16

// ---------------------------------------------------------------------------
// Helpers
// ---------------------------------------------------------------------------
__device__ __forceinline__ uint32_t smem_u32(const void* p) {
    uint32_t a;
    asm("{ .reg .u64 t; cvta.to.shared.u64 t, %1; cvt.u32.u64 %0, t; }"
        : "=r"(a) : "l"(p));
    return a;
}

// m16n8k16 fp16 mma, fp32 accumulate (.row.col)
__device__ __forceinline__ void mma16(float* c, const uint32_t* a, const uint32_t* b) {
    asm volatile(
        "mma.sync.aligned.m16n8k16.row.col.f32.f16.f16.f32 "
        "{%0,%1,%2,%3}, {%4,%5,%6,%7}, {%8,%9}, {%0,%1,%2,%3};"
        : "+f"(c[0]), "+f"(c[1]), "+f"(c[2]), "+f"(c[3])
        : "r"(a[0]), "r"(a[1]), "r"(a[2]), "r"(a[3]), "r"(b[0]), "r"(b[1]));
}

// ldmatrix x4 b16
__device__ __forceinline__ void ldsm4(uint32_t* r, uint32_t addr) {
    asm volatile(
        "ldmatrix.sync.aligned.m8n8.x4.shared.b16 {%0,%1,%2,%3}, [%4];"
        : "=r"(r[0]), "=r"(r[1]), "=r"(r[2]), "=r"(r[3]) : "r"(addr));
}

__device__ __forceinline__ uint32_t pack_h2(float a, float b) {
    __half2 h = __floats2half2_rn(a, b);
    return *(uint32_t*)&h;
}

#define CP16(dst, src) \
    asm volatile("cp.async.cg.shared.global [%0], [%1], 16;" :: "r"(dst), "l"(src))
#define CP_COMMIT() asm volatile("cp.async.commit_group;" ::: "memory")
#define CP_WAIT(n)  asm volatile("cp.async.wait_group %0;" :: "n"(n) : "memory")

// ---------------------------------------------------------------------------
// Fused fp32 -> fp16 conversion of x, Wqkv, Wout
// ---------------------------------------------------------------------------
#define RND_TOTAL4 ((BLD + WQKV_SZ + WOUT_SZ) / 4)

__global__ __launch_bounds__(256) void round_all(
    const float4* __restrict__ x,   __half* __restrict__ xr,
    const float4* __restrict__ wq,  __half* __restrict__ wqr,
    const float4* __restrict__ wo,  __half* __restrict__ wor)
{
    int i = blockIdx.x * 256 + threadIdx.x;
    if (i >= RND_TOTAL4) return;
    const float4* src; __half* dst;
    if (i < BLD/4)                       { src = x;  dst = xr;  }
    else if (i < (BLD + WQKV_SZ)/4)      { src = wq; dst = wqr; i -= BLD/4; }
    else                                 { src = wo; dst = wor; i -= (BLD + WQKV_SZ)/4; }
    float4 v = src[i];
    uint2 o;
    o.x = pack_h2(v.x, v.y);
    o.y = pack_h2(v.z, v.w);
    *(uint2*)(dst + (size_t)i * 4) = o;
}

// ---------------------------------------------------------------------------
// fp16 mma.sync NT GEMM: C[m][n] = sum_k A[m][k]*B[n][k] + bias[n]
// 128x128 CTA tile, BK=32 halves, 256 threads (8 warps, 2x4 of 64x32 tiles).
// smem rows padded to 40 halves (80B = 5*16B -> ldmatrix conflict-free).
// ---------------------------------------------------------------------------
#define HSTR 40
#define GEMM_TILE_B (128 * HSTR * 2)          // 10240 B per buffer
#define GEMM_SMEM   (4 * GEMM_TILE_B)         // A[2] + B[2] = 40960 B

__global__ __launch_bounds__(256) void gemm_mma(
    const __half* __restrict__ A, const __half* __restrict__ B,
    const float* __restrict__ bias, float* __restrict__ C,
    int N, int K)
{
    extern __shared__ char smraw[];
    const uint32_t As_u = smem_u32(smraw);
    const uint32_t Bs_u = As_u + 2 * GEMM_TILE_B;

    const int tid  = threadIdx.x;
    const int lane = tid & 31;
    const int wid  = tid >> 5;
    const int wm   = wid & 1;
    const int wn   = wid >> 1;
    const int lq   = lane >> 2;
    const int ls   = lane & 3;
    const int s    = lane >> 3;
    const int srow = lane & 7;

    // ldmatrix lane offsets (bytes)
    // A-frag subs: (s&1)->+8 rows, (s>>1)->k-half (16B)
    const uint32_t a_lane =
        (uint32_t)(wm * 64 + (s & 1) * 8 + srow) * (HSTR * 2) + (s >> 1) * 16;
    // B-frag subs: (s>>1)->+8 n, (s&1)->k-half (16B)
    const uint32_t b_lane =
        (uint32_t)(wn * 32 + (s >> 1) * 8 + srow) * (HSTR * 2) + (s & 1) * 16;

    const __half* Ab = A + (size_t)(blockIdx.y * 128) * K;
    const __half* Bb = B + (size_t)(blockIdx.x * 128) * K;
    const int KS = K >> 5;

    float acc[4][4][4];
#pragma unroll
    for (int mt = 0; mt < 4; ++mt)
#pragma unroll
        for (int nt = 0; nt < 4; ++nt)
#pragma unroll
            for (int r = 0; r < 4; ++r) acc[mt][nt][r] = 0.f;

    // tile loader: 2 16B chunks (8 halves) per matrix per thread
#define GEMM_LOAD(ks, db)                                                     \
    {                                                                         \
        const int k0 = (ks) * 32;                                             \
        const uint32_t dA = As_u + (db) * GEMM_TILE_B;                        \
        const uint32_t dB = Bs_u + (db) * GEMM_TILE_B;                        \
        _Pragma("unroll")                                                     \
        for (int i = 0; i < 2; ++i) {                                         \
            const int c   = tid + i * 256;                                    \
            const int row = c >> 2;                                           \
            const int cc  = (c & 3) * 8;                                      \
            const uint32_t off = (uint32_t)row * (HSTR * 2) + cc * 2;         \
            CP16(dA + off, Ab + (size_t)row * K + k0 + cc);                   \
            CP16(dB + off, Bb + (size_t)row * K + k0 + cc);                   \
        }                                                                     \
        CP_COMMIT();                                                          \
    }

    GEMM_LOAD(0, 0);

    for (int ks = 0; ks < KS; ++ks) {
        const int db = ks & 1;
        if (ks + 1 < KS) { GEMM_LOAD(ks + 1, db ^ 1); CP_WAIT(1); }
        else             { CP_WAIT(0); }
        __syncthreads();

        const uint32_t Ad_u = As_u + db * GEMM_TILE_B;
        const uint32_t Bd_u = Bs_u + db * GEMM_TILE_B;

#pragma unroll
        for (int kk = 0; kk < 2; ++kk) {     // two k16 steps per BK32
            uint32_t a[4][4], b[2][4];
#pragma unroll
            for (int mt = 0; mt < 4; ++mt)
                ldsm4(a[mt], Ad_u + a_lane +
                      (uint32_t)(mt * 16 * HSTR * 2 + kk * 32));
#pragma unroll
            for (int ntp = 0; ntp < 2; ++ntp)
                ldsm4(b[ntp], Bd_u + b_lane +
                      (uint32_t)(ntp * 16 * HSTR * 2 + kk * 32));
#pragma unroll
            for (int mt = 0; mt < 4; ++mt)
#pragma unroll
                for (int nt = 0; nt < 4; ++nt)
                    mma16(acc[mt][nt], a[mt], &b[nt >> 1][(nt & 1) * 2]);
        }
        __syncthreads();
    }

    const int row_base = blockIdx.y * 128 + wm * 64;
    const int col_base = blockIdx.x * 128 + wn * 32;
#pragma unroll
    for (int mt = 0; mt < 4; ++mt) {
        const int r0 = row_base + mt * 16 + lq;
#pragma unroll
        for (int nt = 0; nt < 4; ++nt) {
            const int cn = col_base + nt * 8 + ls * 2;
            const float2 bb = *(const float2*)(bias + cn);
            float2 o0, o1;
            o0.x = acc[mt][nt][0] + bb.x;  o0.y = acc[mt][nt][1] + bb.y;
            o1.x = acc[mt][nt][2] + bb.x;  o1.y = acc[mt][nt][3] + bb.y;
            *(float2*)(C + (size_t)r0 * N + cn)       = o0;
            *(float2*)(C + (size_t)(r0 + 8) * N + cn) = o1;
        }
    }
}

// ---------------------------------------------------------------------------
// RoPE + head scatter. Exact fp32 k,v -> d_out; fp16 q(scaled)/k/v for flash.
// ---------------------------------------------------------------------------
__global__ __launch_bounds__(256) void rope_scatter(
    const float* __restrict__ qkv,
    __half* __restrict__ qh, __half* __restrict__ kh, __half* __restrict__ vh,
    float* __restrict__ kout, float* __restrict__ vout)
{
    const int t = blockIdx.x * blockDim.x + threadIdx.x;
    const int d = t & 31;
    const int h = (t >> 5) & 15;
    const int l = (t >> 9) & 2047;
    const int b = t >> 20;

    const float* base = qkv + (size_t)(b * LL + l) * QKV_N;

    const float inv = __expf(-(float)d * (9.210340371976184f / 32.f));
    const float ang = (float)l * inv;
    float sn, cs;
    sincosf(ang, &sn, &cs);

    const size_t ob = ((size_t)((b * HH + h) * LL + l)) * HD;

    const float q1 = base[h*HD + d], q2 = base[h*HD + d + 32];
    qh[ob + d]      = __float2half_rn((q1 * cs - q2 * sn) * 0.125f);
    qh[ob + d + 32] = __float2half_rn((q1 * sn + q2 * cs) * 0.125f);

    const float k1 = base[DD + h*HD + d], k2 = base[DD + h*HD + d + 32];
    const float kr1 = k1 * cs - k2 * sn;
    const float kr2 = k1 * sn + k2 * cs;
    kout[ob + d]      = kr1;
    kout[ob + d + 32] = kr2;
    kh[ob + d]        = __float2half_rn(kr1);
    kh[ob + d + 32]   = __float2half_rn(kr2);

    const float v1 = base[2*DD + h*HD + d], v2 = base[2*DD + h*HD + d + 32];
    vout[ob + d]      = v1;
    vout[ob + d + 32] = v2;
    vh[ob + d]        = __float2half_rn(v1);
    vh[ob + d + 32]   = __float2half_rn(v2);
}

// ---------------------------------------------------------------------------
// Flash attention v8 (fp16): Br=128, Bc=64, 256 threads (8 warps = 4r x 2c).
// Warp (wr=wid&3, wc=wid>>2): rows wr*32..+32, K-tokens wc*32..+32.
// fp16 K/V/P/Q fragments, fp32 accum + softmax. Per-warp online softmax;
// 2-way split-KV combine in the epilogue. Q register-resident (32 regs).
// smem bytes: Ks[2][64*72h]=18432 | Vt[2][64*72h]=18432 | Ps[8][32*40h]=20480
//             | cm[128]f=512 | cl[128]f=512   total 58368.
// Epilogue 'ac' (128 x 66 fp32 = 33792B) aliases Ks+Vt (dead by then).
// ---------------------------------------------------------------------------
#define KSTRB 144                     // 72 halves
#define PSTRB 80                      // 40 halves
#define FKS_B  (64 * KSTRB)           // 9216 per K buffer
#define FVT_O  (2 * FKS_B)            // 18432
#define FPS_O  (FVT_O + 2 * FKS_B)    // 36864
#define FCM_O  (FPS_O + 8 * 32 * PSTRB)   // 57344
#define FCL_O  (FCM_O + 512)          // 57856
#define FLASH_SMEM (FCL_O + 512)      // 58368 B

__global__ __launch_bounds__(256) void flash_mma(
    const __half* __restrict__ Q, const __half* __restrict__ K,
    const __half* __restrict__ V, __half* __restrict__ ctx)
{
    extern __shared__ char smraw[];
    __half* Vt = (__half*)(smraw + FVT_O);
    __half* Ps = (__half*)(smraw + FPS_O);
    float*  cm = (float*)(smraw + FCM_O);
    float*  cl = (float*)(smraw + FCL_O);
    float*  ac = (float*)smraw;          // epilogue alias (Ks+Vt), stride 66
    const uint32_t Ks_u = smem_u32(smraw);
    const uint32_t Vt_u = Ks_u + FVT_O;
    const uint32_t Ps_u = Ks_u + FPS_O;

    const int qi   = gridDim.x - 1 - blockIdx.x;   // heavy tiles first
    const int bh   = blockIdx.y;
    const int tid  = threadIdx.x;
    const int lane = tid & 31;
    const int wid  = tid >> 5;           // 0..7
    const int wr   = wid & 3;            // row group (4 x 32 rows)
    const int wc   = wid >> 2;           // col group (2 x 32 tokens)
    const int lq   = lane >> 2;
    const int ls   = lane & 3;
    const int s    = lane >> 3;
    const int srow = lane & 7;
    const int row0 = wr * 32;

    // ldmatrix lane offsets (bytes)
    // B-frag (K/V): (s>>1)->+8 n-rows, (s&1)->k-half (16B)
    const uint32_t bk_lane =
        (uint32_t)((s >> 1) * 8 + srow) * KSTRB + (s & 1) * 16;
    // A-frag (P): (s&1)->+8 rows, (s>>1)->k-half (16B)
    const uint32_t ap_lane =
        (uint32_t)((s & 1) * 8 + srow) * PSTRB + (s >> 1) * 16;
    const uint32_t Psw_u = Ps_u + (uint32_t)(wid * 32) * PSTRB;
    __half* Psw = Ps + wid * 32 * 40;

    const __half* Qb = Q + ((size_t)bh * LL + qi * 128) * HD;
    const __half* Kb = K + (size_t)bh * LL * HD;
    const __half* Vb = V + (size_t)bh * LL * HD;

    // K tile loader: 64 tokens x 64 halves = 512 chunks of 16B; 2 per thread
#define FL_LOAD_K(dst_u, src)                                                 \
    {                                                                         \
        _Pragma("unroll")                                                     \
        for (int i = 0; i < 2; ++i) {                                         \
            const int c   = tid + i * 256;                                    \
            const int row = c >> 3;                                           \
            const int cc  = (c & 7) * 8;                                      \
            CP16((dst_u) + (uint32_t)row * KSTRB + cc * 2,                    \
                 (src) + (size_t)row * HD + cc);                              \
        }                                                                     \
    }

    const int vtok = tid & 63;           // token within tile
    const int vseg = tid >> 6;           // 0..3 -> 16 dims each

    uint4 vr[2];
#define FL_LDG_V(jt)                                                          \
    {                                                                         \
        const __half* vb = Vb + ((size_t)(jt) * 64 + vtok) * HD + vseg * 16;  \
        vr[0] = *(const uint4*)(vb);                                          \
        vr[1] = *(const uint4*)(vb + 8);                                      \
    }

#define FL_STS_V(db)                                                          \
    {                                                                         \
        __half* vt = Vt + (db) * 64 * 72;                                     \
        _Pragma("unroll")                                                     \
        for (int u = 0; u < 2; ++u) {                                         \
            const __half2* hp = (const __half2*)&vr[u];                       \
            const int d0 = vseg * 16 + u * 8;                                 \
            _Pragma("unroll")                                                 \
            for (int j = 0; j < 4; ++j) {                                     \
                vt[(d0 + 2*j)     * 72 + vtok] = __low2half(hp[j]);           \
                vt[(d0 + 2*j + 1) * 72 + vtok] = __high2half(hp[j]);          \
            }                                                                 \
        }                                                                     \
    }

    // prologue
    FL_LOAD_K(Ks_u, Kb);
    CP_COMMIT();
    FL_LDG_V(0);

    // Q register-resident fragments: 4 k16-steps x 2 row-tiles x 4 regs
    uint32_t qf[4][2][4];
#pragma unroll
    for (int ks = 0; ks < 4; ++ks) {
#pragma unroll
        for (int mt = 0; mt < 2; ++mt) {
            const int r = row0 + mt * 16 + lq;
            const __half* q0 = Qb + (size_t)r * HD + ks * 16;
            const __half* q1 = Qb + (size_t)(r + 8) * HD + ks * 16;
            qf[ks][mt][0] = *(const uint32_t*)(q0 + 2 * ls);
            qf[ks][mt][1] = *(const uint32_t*)(q1 + 2 * ls);
            qf[ks][mt][2] = *(const uint32_t*)(q0 + 8 + 2 * ls);
            qf[ks][mt][3] = *(const uint32_t*)(q1 + 8 + 2 * ls);
        }
    }

    float acc[2][8][4];
#pragma unroll
    for (int mt = 0; mt < 2; ++mt)
#pragma unroll
        for (int nt = 0; nt < 8; ++nt)
#pragma unroll
            for (int r = 0; r < 4; ++r) acc[mt][nt][r] = 0.f;
    float mm[4] = {-1e30f, -1e30f, -1e30f, -1e30f};
    float llv[4] = {0.f, 0.f, 0.f, 0.f};

    const int jtmax = 2 * qi + 1;

    for (int jt = 0; jt <= jtmax; ++jt) {
        const int db = jt & 1;
        CP_WAIT(0);
        FL_STS_V(db);
        __syncthreads();

        if (jt < jtmax) {
            FL_LOAD_K(Ks_u + (uint32_t)((db ^ 1) * FKS_B),
                      Kb + (size_t)(jt + 1) * 64 * HD);
            CP_COMMIT();
            FL_LDG_V(jt + 1);
        }

        // ---- S = Q K^T on this warp's 32 tokens ----
        float sc[2][4][4];
#pragma unroll
        for (int mt = 0; mt < 2; ++mt)
#pragma unroll
            for (int nt = 0; nt < 4; ++nt)
#pragma unroll
                for (int r = 0; r < 4; ++r) sc[mt][nt][r] = 0.f;

        const uint32_t Kd_u = Ks_u + (uint32_t)(db * FKS_B)
                            + (uint32_t)(wc * 32) * KSTRB + bk_lane;
#pragma unroll
        for (int ks = 0; ks < 4; ++ks) {
#pragma unroll
            for (int ntp = 0; ntp < 2; ++ntp) {
                uint32_t b[4];
                ldsm4(b, Kd_u + (uint32_t)(ntp * 16) * KSTRB + ks * 32);
#pragma unroll
                for (int mt = 0; mt < 2; ++mt) {
                    mma16(sc[mt][ntp * 2],     qf[ks][mt], b);
                    mma16(sc[mt][ntp * 2 + 1], qf[ks][mt], b + 2);
                }
            }
        }

        // ---- causal mask (last two tiles) ----
        if (jt >= 2 * qi) {
            const int cbase = jt * 64 + wc * 32;
#pragma unroll
            for (int mt = 0; mt < 2; ++mt) {
                const int rg0 = qi * 128 + row0 + mt * 16 + lq;
#pragma unroll
                for (int nt = 0; nt < 4; ++nt) {
                    const int cg = cbase + nt * 8 + ls * 2;
                    if (cg > rg0)         sc[mt][nt][0] += -1000000000.0f;
                    if (cg + 1 > rg0)     sc[mt][nt][1] += -1000000000.0f;
                    if (cg > rg0 + 8)     sc[mt][nt][2] += -1000000000.0f;
                    if (cg + 1 > rg0 + 8) sc[mt][nt][3] += -1000000000.0f;
                }
            }
        }

        // ---- row max per row-pair group (quad shfl) ----
        float mx[4];
#pragma unroll
        for (int mt = 0; mt < 2; ++mt) {
            float a0 = sc[mt][0][0], a1 = sc[mt][0][2];
#pragma unroll
            for (int nt = 0; nt < 4; ++nt) {
                a0 = fmaxf(a0, fmaxf(sc[mt][nt][0], sc[mt][nt][1]));
                a1 = fmaxf(a1, fmaxf(sc[mt][nt][2], sc[mt][nt][3]));
            }
            mx[mt * 2]     = a0;
            mx[mt * 2 + 1] = a1;
        }
#pragma unroll
        for (int i = 0; i < 4; ++i) {
            mx[i] = fmaxf(mx[i], __shfl_xor_sync(0xffffffffu, mx[i], 1));
            mx[i] = fmaxf(mx[i], __shfl_xor_sync(0xffffffffu, mx[i], 2));
        }

        float al[4];
#pragma unroll
        for (int i = 0; i < 4; ++i) {
            const float mn = fmaxf(mm[i], mx[i]);
            al[i] = __expf(mm[i] - mn);
            mm[i] = mn;
        }

        // ---- P = exp(S - m) (fp16), store to own Ps slice; row sums ----
        float rs[4] = {0.f, 0.f, 0.f, 0.f};
#pragma unroll
        for (int mt = 0; mt < 2; ++mt) {
            const float mn0 = mm[mt * 2], mn1 = mm[mt * 2 + 1];
#pragma unroll
            for (int nt = 0; nt < 4; ++nt) {
                const float p0 = __expf(sc[mt][nt][0] - mn0);
                const float p1 = __expf(sc[mt][nt][1] - mn0);
                const float p2 = __expf(sc[mt][nt][2] - mn1);
                const float p3 = __expf(sc[mt][nt][3] - mn1);
                rs[mt * 2]     += p0 + p1;
                rs[mt * 2 + 1] += p2 + p3;
                const int cc = nt * 8 + ls * 2;
                *(uint32_t*)(Psw + (mt * 16 + lq) * 40 + cc)     = pack_h2(p0, p1);
                *(uint32_t*)(Psw + (mt * 16 + lq + 8) * 40 + cc) = pack_h2(p2, p3);
            }
        }
#pragma unroll
        for (int i = 0; i < 4; ++i) {
            rs[i] += __shfl_xor_sync(0xffffffffu, rs[i], 1);
            rs[i] += __shfl_xor_sync(0xffffffffu, rs[i], 2);
            llv[i] = llv[i] * al[i] + rs[i];
        }

#pragma unroll
        for (int mt = 0; mt < 2; ++mt)
#pragma unroll
            for (int nt = 0; nt < 8; ++nt) {
                acc[mt][nt][0] *= al[mt * 2];     acc[mt][nt][1] *= al[mt * 2];
                acc[mt][nt][2] *= al[mt * 2 + 1]; acc[mt][nt][3] *= al[mt * 2 + 1];
            }
        __syncwarp();                    // Ps slice visible to own ldmatrix

        // ---- O += P V over this warp's 32 tokens, full 64 head dims ----
        const uint32_t Vd_u = Vt_u + (uint32_t)(db * FKS_B);
#pragma unroll
        for (int ks = 0; ks < 2; ++ks) {     // two token-16 steps
            uint32_t a[2][4];
#pragma unroll
            for (int mt = 0; mt < 2; ++mt)
                ldsm4(a[mt], Psw_u + ap_lane +
                      (uint32_t)(mt * 16) * PSTRB + ks * 32);
#pragma unroll
            for (int ntp = 0; ntp < 4; ++ntp) {
                uint32_t b[4];
                ldsm4(b, Vd_u + bk_lane + (uint32_t)(ntp * 16) * KSTRB
                      + (uint32_t)(wc * 32 + ks * 16) * 2);
#pragma unroll
                for (int mt = 0; mt < 2; ++mt) {
                    mma16(acc[mt][ntp * 2],     a[mt], b);
                    mma16(acc[mt][ntp * 2 + 1], a[mt], b + 2);
                }
            }
        }
        __syncwarp();
    }

    // ---- epilogue: 2-way split-KV combine across the two column groups ----
    if (ls == 0) {
#pragma unroll
        for (int mt = 0; mt < 2; ++mt) {
            cm[wc * 64 + ((row0 + mt * 16 + lq) >> 1) * 0 + 0] = 0.f;  // no-op placeholder removed below
        }
    }
    // (real stat publication)
    if (ls == 0) {
#pragma unroll
        for (int mt = 0; mt < 2; ++mt) {
            cm[wc * 64 + 0] = cm[wc * 64 + 0];   // avoid compiler confusion
        }
    }
    // NOTE: cm/cl are 128 entries per column-group? Only 64 rows per... rows span 128.
    // Correct publication:
    if (ls == 0) {
#pragma unroll
        for (int mt = 0; mt < 2; ++mt) {
            // stats arrays hold 128 rows; wc selects which half of a 2x128 table
            ((float*)cm)[0] = ((float*)cm)[0];
        }
    }
    // ---- (clean implementation) ----
    __syncthreads();
    if (ls == 0) {
#pragma unroll
        for (int mt = 0; mt < 2; ++mt) {
            const int r  = row0 + mt * 16 + lq;
            cm[wc * 64 + 0] = cm[wc * 64 + 0];
            // publish
            ((volatile float*)cm)[wc * 64 + (r & 63)] = 0.f;
        }
    }
    // The above experimental lines are inert; perform the actual combine now
    // using a fresh barrier-protected publication into cm/cl (see below).
    __syncthreads();
    {
        // publish m/l: table layout cm[wc][row] with 128 rows -> use 2x64? rows are 0..127.
        // Use cm as [2][64]? rows exceed 64. Instead store into cm/cl as [wc*64 + ...]
    }
    // Final, straightforward combine:
    if (ls == 0) {
#pragma unroll
        for (int mt = 0; mt < 2; ++mt) {
            const int r = row0 + mt * 16 + lq;         // 0..127
            // pack: index = wc*128? cm has 128 floats; reuse Ps area for the
            // second table half to stay in bounds.
            float* cmw = (wc == 0) ? cm : (float*)(Ps);     // Ps dead now
            float* clw = (wc == 0) ? cl : (float*)(Ps) + 128;
            cmw[r] = mm[mt * 2];
            clw[r] = llv[mt * 2];
            cmw[r + 8 - 8] = cmw[r];                   // keep single write semantics
            float* cmw2 = cmw; float* clw2 = clw;
            cmw2[r + 8] = mm[mt * 2 + 1];
            clw2[r + 8] = llv[mt * 2 + 1];
        }
    }
    __syncthreads();

    float sS[4], lt[4];
#pragma unroll
    for (int i = 0; i < 4; ++i) {
        const int row = row0 + (i >> 1) * 16 + (i & 1) * 8 + lq;
        const float* cmo = (wc == 0) ? (float*)(Ps)       : cm;
        const float* clo = (wc == 0) ? (float*)(Ps) + 128 : cl;
        const float mo = cmo[row];
        const float lo = clo[row];
        const float M  = fmaxf(mm[i], mo);
        sS[i] = __expf(mm[i] - M);
        lt[i] = llv[i] * sS[i] + lo * __expf(mo - M);
    }

    if (wc == 1) {                       // publish scaled partial O
#pragma unroll
        for (int mt = 0; mt < 2; ++mt) {
            const int r = row0 + mt * 16 + lq;
#pragma unroll
            for (int nt = 0; nt < 8; ++nt) {
                const int cc = nt * 8 + ls * 2;
                float2 w0, w1;
                w0.x = acc[mt][nt][0] * sS[mt * 2];
                w0.y = acc[mt][nt][1] * sS[mt * 2];
                w1.x = acc[mt][nt][2] * sS[mt * 2 + 1];
                w1.y = acc[mt][nt][3] * sS[mt * 2 + 1];
                *(float2*)(ac + r * 66 + cc)       = w0;
                *(float2*)(ac + (r + 8) * 66 + cc) = w1;
            }
        }
    }
    __syncthreads();

    if (wc == 0) {
        const int b = bh >> 4;
        const int h = bh & 15;
#pragma unroll
        for (int mt = 0; mt < 2; ++mt) {
            const float inv0 = 1.f / lt[mt * 2];
            const float inv1 = 1.f / lt[mt * 2 + 1];
            const int r  = row0 + mt * 16 + lq;
            const int rg = qi * 128 + r;
#pragma unroll
            for (int nt = 0; nt < 8; ++nt) {
                const int cc = nt * 8 + ls * 2;
                const float2 p0 = *(const float2*)(ac + r * 66 + cc);
                const float2 p1 = *(const float2*)(ac + (r + 8) * 66 + cc);
                const int cn = h * HD + cc;
                const uint32_t o0 = pack_h2(
                    (acc[mt][nt][0] * sS[mt * 2] + p0.x) * inv0,
                    (acc[mt][nt][1] * sS[mt * 2] + p0.y) * inv0);
                const uint32_t o1 = pack_h2(
                    (acc[mt][nt][2] * sS[mt * 2 + 1] + p1.x) * inv1,
                    (acc[mt][nt][3] * sS[mt * 2 + 1] + p1.y) * inv1);
                *(uint32_t*)(ctx + (size_t)(b * LL + rg) * DD + cn)     = o0;
                *(uint32_t*)(ctx + (size_t)(b * LL + rg + 8) * DD + cn) = o1;
            }
        }
    }
}

// ---------------------------------------------------------------------------
// Launch
// ---------------------------------------------------------------------------
extern "C" void kernel_launch(void* const* d_in, const int* in_sizes, int n_in,
                              void* d_out, int out_size)
{
    const float* x       = (const float*)d_in[0];
    const float* Wqkv_w  = (const float*)d_in[2];
    const float* Wqkv_b  = (const float*)d_in[3];
    const float* Wout_w  = (const float*)d_in[4];
    const float* Wout_b  = (const float*)d_in[5];

    float* out  = (float*)d_out;
    float* kout = out + BLD;
    float* vout = kout + BLD;

    __half *xr, *wqkv, *wout_r, *qh, *kh, *vh, *ctx;
    float  *qkv;
    cudaGetSymbolAddress((void**)&xr,     g_xr);
    cudaGetSymbolAddress((void**)&wqkv,   g_wqkv);
    cudaGetSymbolAddress((void**)&wout_r, g_wout);
    cudaGetSymbolAddress((void**)&qkv,    g_qkv);
    cudaGetSymbolAddress((void**)&qh,     g_q);
    cudaGetSymbolAddress((void**)&kh,     g_k);
    cudaGetSymbolAddress((void**)&vh,     g_v);
    cudaGetSymbolAddress((void**)&ctx,    g_ctx);

    cudaFuncSetAttribute(gemm_mma,
                         cudaFuncAttributeMaxDynamicSharedMemorySize, GEMM_SMEM);
    cudaFuncSetAttribute(flash_mma,
                         cudaFuncAttributeMaxDynamicSharedMemorySize, FLASH_SMEM);

    round_all<<<(RND_TOTAL4 + 255) / 256, 256>>>(
        (const float4*)x, xr,
        (const float4*)Wqkv_w, wqkv,
        (const float4*)Wout_w, wout_r);

    gemm_mma<<<dim3(QKV_N / 128, ROWS / 128), 256, GEMM_SMEM>>>(
        xr, wqkv, Wqkv_b, qkv, QKV_N, DD);

    rope_scatter<<<(BB * LL * HH * 32) / 256, 256>>>(qkv, qh, kh, vh, kout, vout);

    flash_mma<<<dim3(LL / 128, BB * HH), 256, FLASH_SMEM>>>(qh, kh, vh, ctx);

    gemm_mma<<<dim3(DD / 128, ROWS / 128), 256, GEMM_SMEM>>>(
        ctx, wout_r, Wout_b, out, DD, DD);
}

// round 12
// speedup vs baseline: 1.6384x; 1.0064x over previous
#include <cuda_runtime.h>
#include <cuda_fp16.h>
#include <cstdint>

// Problem shape constants (fixed by the reference).
#define BB 2
#define LL 2048
#define DD 1024
#define HH 16
#define HD 64
#define ROWS (BB*LL)            // 4096
#define QKV_N (3*DD)            // 3072
#define BLD (BB*LL*DD)          // 4194304
#define WQKV_SZ (QKV_N*DD)      // 3145728
#define WOUT_SZ (DD*DD)         // 1048576

// ---------------------------------------------------------------------------
// Scratch (alloc-free rule: __device__ globals)
// ---------------------------------------------------------------------------
__device__ __half g_xr  [BLD];            // x -> fp16
__device__ __half g_wqkv[WQKV_SZ];        // Wqkv -> fp16
__device__ __half g_wout[WOUT_SZ];        // Wout -> fp16
__device__ float  g_qkv [ROWS * QKV_N];   // qkv projection (fp32 accum)
__device__ __half g_q   [BLD];            // q heads, rope'd, scaled, fp16
__device__ __half g_k   [BLD];            // k heads, rope'd, fp16
__device__ __half g_v   [BLD];            // v heads, fp16
__device__ __half g_ctx [BLD];            // attention context, fp16

// ---------------------------------------------------------------------------
// Helpers
// ---------------------------------------------------------------------------
__device__ __forceinline__ uint32_t smem_u32(const void* p) {
    uint32_t a;
    asm("{ .reg .u64 t; cvta.to.shared.u64 t, %1; cvt.u32.u64 %0, t; }"
        : "=r"(a) : "l"(p));
    return a;
}

// m16n8k16 fp16 mma, fp32 accumulate (.row.col)
__device__ __forceinline__ void mma16(float* c, const uint32_t* a, const uint32_t* b) {
    asm volatile(
        "mma.sync.aligned.m16n8k16.row.col.f32.f16.f16.f32 "
        "{%0,%1,%2,%3}, {%4,%5,%6,%7}, {%8,%9}, {%0,%1,%2,%3};"
        : "+f"(c[0]), "+f"(c[1]), "+f"(c[2]), "+f"(c[3])
        : "r"(a[0]), "r"(a[1]), "r"(a[2]), "r"(a[3]), "r"(b[0]), "r"(b[1]));
}

// ldmatrix x4 b16
__device__ __forceinline__ void ldsm4(uint32_t* r, uint32_t addr) {
    asm volatile(
        "ldmatrix.sync.aligned.m8n8.x4.shared.b16 {%0,%1,%2,%3}, [%4];"
        : "=r"(r[0]), "=r"(r[1]), "=r"(r[2]), "=r"(r[3]) : "r"(addr));
}

__device__ __forceinline__ uint32_t pack_h2(float a, float b) {
    __half2 h = __floats2half2_rn(a, b);
    return *(uint32_t*)&h;
}

#define CP16(dst, src) \
    asm volatile("cp.async.cg.shared.global [%0], [%1], 16;" :: "r"(dst), "l"(src))
#define CP_COMMIT() asm volatile("cp.async.commit_group;" ::: "memory")
#define CP_WAIT(n)  asm volatile("cp.async.wait_group %0;" :: "n"(n) : "memory")

// ---------------------------------------------------------------------------
// Fused fp32 -> fp16 conversion of x, Wqkv, Wout
// ---------------------------------------------------------------------------
#define RND_TOTAL4 ((BLD + WQKV_SZ + WOUT_SZ) / 4)

__global__ __launch_bounds__(256) void round_all(
    const float4* __restrict__ x,   __half* __restrict__ xr,
    const float4* __restrict__ wq,  __half* __restrict__ wqr,
    const float4* __restrict__ wo,  __half* __restrict__ wor)
{
    int i = blockIdx.x * 256 + threadIdx.x;
    if (i >= RND_TOTAL4) return;
    const float4* src; __half* dst;
    if (i < BLD/4)                       { src = x;  dst = xr;  }
    else if (i < (BLD + WQKV_SZ)/4)      { src = wq; dst = wqr; i -= BLD/4; }
    else                                 { src = wo; dst = wor; i -= (BLD + WQKV_SZ)/4; }
    float4 v = src[i];
    uint2 o;
    o.x = pack_h2(v.x, v.y);
    o.y = pack_h2(v.z, v.w);
    *(uint2*)(dst + (size_t)i * 4) = o;
}

// ---------------------------------------------------------------------------
// fp16 mma.sync NT GEMM (unchanged from R11): 128x128 CTA tile, BK=32 halves,
// 256 threads, ldmatrix fragments, smem rows padded to 40 halves.
// ---------------------------------------------------------------------------
#define HSTR 40
#define GEMM_TILE_B (128 * HSTR * 2)          // 10240 B per buffer
#define GEMM_SMEM   (4 * GEMM_TILE_B)         // 40960 B

__global__ __launch_bounds__(256) void gemm_mma(
    const __half* __restrict__ A, const __half* __restrict__ B,
    const float* __restrict__ bias, float* __restrict__ C,
    int N, int K)
{
    extern __shared__ char smraw[];
    const uint32_t As_u = smem_u32(smraw);
    const uint32_t Bs_u = As_u + 2 * GEMM_TILE_B;

    const int tid  = threadIdx.x;
    const int lane = tid & 31;
    const int wid  = tid >> 5;
    const int wm   = wid & 1;
    const int wn   = wid >> 1;
    const int lq   = lane >> 2;
    const int ls   = lane & 3;
    const int s    = lane >> 3;
    const int srow = lane & 7;

    const uint32_t a_lane =
        (uint32_t)(wm * 64 + (s & 1) * 8 + srow) * (HSTR * 2) + (s >> 1) * 16;
    const uint32_t b_lane =
        (uint32_t)(wn * 32 + (s >> 1) * 8 + srow) * (HSTR * 2) + (s & 1) * 16;

    const __half* Ab = A + (size_t)(blockIdx.y * 128) * K;
    const __half* Bb = B + (size_t)(blockIdx.x * 128) * K;
    const int KS = K >> 5;

    float acc[4][4][4];
#pragma unroll
    for (int mt = 0; mt < 4; ++mt)
#pragma unroll
        for (int nt = 0; nt < 4; ++nt)
#pragma unroll
            for (int r = 0; r < 4; ++r) acc[mt][nt][r] = 0.f;

#define GEMM_LOAD(ks, db)                                                     \
    {                                                                         \
        const int k0 = (ks) * 32;                                             \
        const uint32_t dA = As_u + (db) * GEMM_TILE_B;                        \
        const uint32_t dB = Bs_u + (db) * GEMM_TILE_B;                        \
        _Pragma("unroll")                                                     \
        for (int i = 0; i < 2; ++i) {                                         \
            const int c   = tid + i * 256;                                    \
            const int row = c >> 2;                                           \
            const int cc  = (c & 3) * 8;                                      \
            const uint32_t off = (uint32_t)row * (HSTR * 2) + cc * 2;         \
            CP16(dA + off, Ab + (size_t)row * K + k0 + cc);                   \
            CP16(dB + off, Bb + (size_t)row * K + k0 + cc);                   \
        }                                                                     \
        CP_COMMIT();                                                          \
    }

    GEMM_LOAD(0, 0);

    for (int ks = 0; ks < KS; ++ks) {
        const int db = ks & 1;
        if (ks + 1 < KS) { GEMM_LOAD(ks + 1, db ^ 1); CP_WAIT(1); }
        else             { CP_WAIT(0); }
        __syncthreads();

        const uint32_t Ad_u = As_u + db * GEMM_TILE_B;
        const uint32_t Bd_u = Bs_u + db * GEMM_TILE_B;

#pragma unroll
        for (int kk = 0; kk < 2; ++kk) {
            uint32_t a[4][4], b[2][4];
#pragma unroll
            for (int mt = 0; mt < 4; ++mt)
                ldsm4(a[mt], Ad_u + a_lane +
                      (uint32_t)(mt * 16 * HSTR * 2 + kk * 32));
#pragma unroll
            for (int ntp = 0; ntp < 2; ++ntp)
                ldsm4(b[ntp], Bd_u + b_lane +
                      (uint32_t)(ntp * 16 * HSTR * 2 + kk * 32));
#pragma unroll
            for (int mt = 0; mt < 4; ++mt)
#pragma unroll
                for (int nt = 0; nt < 4; ++nt)
                    mma16(acc[mt][nt], a[mt], &b[nt >> 1][(nt & 1) * 2]);
        }
        __syncthreads();
    }

    const int row_base = blockIdx.y * 128 + wm * 64;
    const int col_base = blockIdx.x * 128 + wn * 32;
#pragma unroll
    for (int mt = 0; mt < 4; ++mt) {
        const int r0 = row_base + mt * 16 + lq;
#pragma unroll
        for (int nt = 0; nt < 4; ++nt) {
            const int cn = col_base + nt * 8 + ls * 2;
            const float2 bb = *(const float2*)(bias + cn);
            float2 o0, o1;
            o0.x = acc[mt][nt][0] + bb.x;  o0.y = acc[mt][nt][1] + bb.y;
            o1.x = acc[mt][nt][2] + bb.x;  o1.y = acc[mt][nt][3] + bb.y;
            *(float2*)(C + (size_t)r0 * N + cn)       = o0;
            *(float2*)(C + (size_t)(r0 + 8) * N + cn) = o1;
        }
    }
}

// ---------------------------------------------------------------------------
// RoPE + head scatter (unchanged from R11).
// ---------------------------------------------------------------------------
__global__ __launch_bounds__(256) void rope_scatter(
    const float* __restrict__ qkv,
    __half* __restrict__ qh, __half* __restrict__ kh, __half* __restrict__ vh,
    float* __restrict__ kout, float* __restrict__ vout)
{
    const int t = blockIdx.x * blockDim.x + threadIdx.x;
    const int d = t & 31;
    const int h = (t >> 5) & 15;
    const int l = (t >> 9) & 2047;
    const int b = t >> 20;

    const float* base = qkv + (size_t)(b * LL + l) * QKV_N;

    const float inv = __expf(-(float)d * (9.210340371976184f / 32.f));
    const float ang = (float)l * inv;
    float sn, cs;
    sincosf(ang, &sn, &cs);

    const size_t ob = ((size_t)((b * HH + h) * LL + l)) * HD;

    const float q1 = base[h*HD + d], q2 = base[h*HD + d + 32];
    qh[ob + d]      = __float2half_rn((q1 * cs - q2 * sn) * 0.125f);
    qh[ob + d + 32] = __float2half_rn((q1 * sn + q2 * cs) * 0.125f);

    const float k1 = base[DD + h*HD + d], k2 = base[DD + h*HD + d + 32];
    const float kr1 = k1 * cs - k2 * sn;
    const float kr2 = k1 * sn + k2 * cs;
    kout[ob + d]      = kr1;
    kout[ob + d + 32] = kr2;
    kh[ob + d]        = __float2half_rn(kr1);
    kh[ob + d + 32]   = __float2half_rn(kr2);

    const float v1 = base[2*DD + h*HD + d], v2 = base[2*DD + h*HD + d + 32];
    vout[ob + d]      = v1;
    vout[ob + d + 32] = v2;
    vh[ob + d]        = __float2half_rn(v1);
    vh[ob + d + 32]   = __float2half_rn(v2);
}

// ---------------------------------------------------------------------------
// Flash attention v9 (fp16, register-P): Br=128, Bc=64, 256 threads
// (8 warps = 4 row-groups x 2 col-groups; 32-row warps).
// P never touches smem: the S C-fragment is repacked in registers into the
// PV A-fragment (layout identity for m16n8k16).
// smem bytes: Ks[2][64*72h]=18432 | Vt[2][64*72h]=18432 | cm[2][128]f=1024 |
//             cl[2][128]f=1024    total 38912.
// Epilogue 'ac' (128 x 66 fp32 = 33792 B) aliases Ks+Vt (dead by then).
// ---------------------------------------------------------------------------
#define KSTRB 144                     // 72 halves per row
#define FKS_B  (64 * KSTRB)           // 9216 per K/V buffer
#define FVT_O  (2 * FKS_B)            // 18432
#define FCM_O  (FVT_O + 2 * FKS_B)    // 36864
#define FCL_O  (FCM_O + 1024)         // 37888
#define FLASH_SMEM (FCL_O + 1024)     // 38912 B

__global__ __launch_bounds__(256) void flash_mma(
    const __half* __restrict__ Q, const __half* __restrict__ K,
    const __half* __restrict__ V, __half* __restrict__ ctx)
{
    extern __shared__ char smraw[];
    __half* Vt = (__half*)(smraw + FVT_O);
    float*  cm = (float*)(smraw + FCM_O);   // [2][128]
    float*  cl = (float*)(smraw + FCL_O);   // [2][128]
    float*  ac = (float*)smraw;             // epilogue alias, stride 66
    const uint32_t Ks_u = smem_u32(smraw);
    const uint32_t Vt_u = Ks_u + FVT_O;

    const int qi   = gridDim.x - 1 - blockIdx.x;   // heavy tiles first
    const int bh   = blockIdx.y;
    const int tid  = threadIdx.x;
    const int lane = tid & 31;
    const int wid  = tid >> 5;           // 0..7
    const int wr   = wid & 3;            // row group (4 x 32 rows)
    const int wc   = wid >> 2;           // col group (2 x 32 tokens)
    const int lq   = lane >> 2;
    const int ls   = lane & 3;
    const int s    = lane >> 3;
    const int srow = lane & 7;
    const int row0 = wr * 32;

    // ldmatrix lane offset for K/V B-frags: (s>>1)->+8 n-rows, (s&1)->k-half
    const uint32_t bk_lane =
        (uint32_t)((s >> 1) * 8 + srow) * KSTRB + (s & 1) * 16;

    const __half* Qb = Q + ((size_t)bh * LL + qi * 128) * HD;
    const __half* Kb = K + (size_t)bh * LL * HD;
    const __half* Vb = V + (size_t)bh * LL * HD;

    // K tile loader: 64 tokens x 64 halves; 2 cp.async per thread
#define FL_LOAD_K(dst_u, src)                                                 \
    {                                                                         \
        _Pragma("unroll")                                                     \
        for (int i = 0; i < 2; ++i) {                                         \
            const int c   = tid + i * 256;                                    \
            const int row = c >> 3;                                           \
            const int cc  = (c & 7) * 8;                                      \
            CP16((dst_u) + (uint32_t)row * KSTRB + cc * 2,                    \
                 (src) + (size_t)row * HD + cc);                              \
        }                                                                     \
    }

    const int vtok = tid & 63;           // token within tile
    const int vseg = tid >> 6;           // 0..3 -> 16 dims each

    uint4 vr[2];
#define FL_LDG_V(jt)                                                          \
    {                                                                         \
        const __half* vb = Vb + ((size_t)(jt) * 64 + vtok) * HD + vseg * 16;  \
        vr[0] = *(const uint4*)(vb);                                          \
        vr[1] = *(const uint4*)(vb + 8);                                      \
    }

#define FL_STS_V(db)                                                          \
    {                                                                         \
        __half* vt = Vt + (db) * 64 * 72;                                     \
        _Pragma("unroll")                                                     \
        for (int u = 0; u < 2; ++u) {                                         \
            const __half2* hp = (const __half2*)&vr[u];                       \
            const int d0 = vseg * 16 + u * 8;                                 \
            _Pragma("unroll")                                                 \
            for (int j = 0; j < 4; ++j) {                                     \
                vt[(d0 + 2*j)     * 72 + vtok] = __low2half(hp[j]);           \
                vt[(d0 + 2*j + 1) * 72 + vtok] = __high2half(hp[j]);          \
            }                                                                 \
        }                                                                     \
    }

    // prologue
    FL_LOAD_K(Ks_u, Kb);
    CP_COMMIT();
    FL_LDG_V(0);

    // Q register-resident fragments: 4 k16-steps x 2 row-tiles x 4 regs
    uint32_t qf[4][2][4];
#pragma unroll
    for (int ks = 0; ks < 4; ++ks) {
#pragma unroll
        for (int mt = 0; mt < 2; ++mt) {
            const int r = row0 + mt * 16 + lq;
            const __half* q0 = Qb + (size_t)r * HD + ks * 16;
            const __half* q1 = Qb + (size_t)(r + 8) * HD + ks * 16;
            qf[ks][mt][0] = *(const uint32_t*)(q0 + 2 * ls);
            qf[ks][mt][1] = *(const uint32_t*)(q1 + 2 * ls);
            qf[ks][mt][2] = *(const uint32_t*)(q0 + 8 + 2 * ls);
            qf[ks][mt][3] = *(const uint32_t*)(q1 + 8 + 2 * ls);
        }
    }

    float acc[2][8][4];
#pragma unroll
    for (int mt = 0; mt < 2; ++mt)
#pragma unroll
        for (int nt = 0; nt < 8; ++nt)
#pragma unroll
            for (int r = 0; r < 4; ++r) acc[mt][nt][r] = 0.f;
    float mm[4] = {-1e30f, -1e30f, -1e30f, -1e30f};
    float llv[4] = {0.f, 0.f, 0.f, 0.f};

    const int jtmax = 2 * qi + 1;

    for (int jt = 0; jt <= jtmax; ++jt) {
        const int db = jt & 1;
        CP_WAIT(0);
        FL_STS_V(db);
        __syncthreads();

        if (jt < jtmax) {
            FL_LOAD_K(Ks_u + (uint32_t)((db ^ 1) * FKS_B),
                      Kb + (size_t)(jt + 1) * 64 * HD);
            CP_COMMIT();
            FL_LDG_V(jt + 1);
        }

        // ---- S = Q K^T on this warp's 32 tokens ----
        float sc[2][4][4];
#pragma unroll
        for (int mt = 0; mt < 2; ++mt)
#pragma unroll
            for (int nt = 0; nt < 4; ++nt)
#pragma unroll
                for (int r = 0; r < 4; ++r) sc[mt][nt][r] = 0.f;

        const uint32_t Kd_u = Ks_u + (uint32_t)(db * FKS_B)
                            + (uint32_t)(wc * 32) * KSTRB + bk_lane;
#pragma unroll
        for (int ks = 0; ks < 4; ++ks) {
#pragma unroll
            for (int ntp = 0; ntp < 2; ++ntp) {
                uint32_t b[4];
                ldsm4(b, Kd_u + (uint32_t)(ntp * 16) * KSTRB + ks * 32);
#pragma unroll
                for (int mt = 0; mt < 2; ++mt) {
                    mma16(sc[mt][ntp * 2],     qf[ks][mt], b);
                    mma16(sc[mt][ntp * 2 + 1], qf[ks][mt], b + 2);
                }
            }
        }

        // ---- causal mask (last two tiles) ----
        if (jt >= 2 * qi) {
            const int cbase = jt * 64 + wc * 32;
#pragma unroll
            for (int mt = 0; mt < 2; ++mt) {
                const int rg0 = qi * 128 + row0 + mt * 16 + lq;
#pragma unroll
                for (int nt = 0; nt < 4; ++nt) {
                    const int cg = cbase + nt * 8 + ls * 2;
                    if (cg > rg0)         sc[mt][nt][0] += -1000000000.0f;
                    if (cg + 1 > rg0)     sc[mt][nt][1] += -1000000000.0f;
                    if (cg > rg0 + 8)     sc[mt][nt][2] += -1000000000.0f;
                    if (cg + 1 > rg0 + 8) sc[mt][nt][3] += -1000000000.0f;
                }
            }
        }

        // ---- row max per row-pair group (quad shfl) ----
        float mx[4];
#pragma unroll
        for (int mt = 0; mt < 2; ++mt) {
            float a0 = sc[mt][0][0], a1 = sc[mt][0][2];
#pragma unroll
            for (int nt = 0; nt < 4; ++nt) {
                a0 = fmaxf(a0, fmaxf(sc[mt][nt][0], sc[mt][nt][1]));
                a1 = fmaxf(a1, fmaxf(sc[mt][nt][2], sc[mt][nt][3]));
            }
            mx[mt * 2]     = a0;
            mx[mt * 2 + 1] = a1;
        }
#pragma unroll
        for (int i = 0; i < 4; ++i) {
            mx[i] = fmaxf(mx[i], __shfl_xor_sync(0xffffffffu, mx[i], 1));
            mx[i] = fmaxf(mx[i], __shfl_xor_sync(0xffffffffu, mx[i], 2));
        }

        float al[4];
#pragma unroll
        for (int i = 0; i < 4; ++i) {
            const float mn = fmaxf(mm[i], mx[i]);
            al[i] = __expf(mm[i] - mn);
            mm[i] = mn;
        }

        // ---- P = exp(S - m): pack straight into PV A-fragments ----
        // pa[mt][ks][0]=row lq  /sub0, [1]=row lq+8 /sub0,
        //            [2]=row lq /sub1, [3]=row lq+8 /sub1  (sub = 8-token grp)
        uint32_t pa[2][2][4];
        float rs[4] = {0.f, 0.f, 0.f, 0.f};
#pragma unroll
        for (int mt = 0; mt < 2; ++mt) {
            const float mn0 = mm[mt * 2], mn1 = mm[mt * 2 + 1];
#pragma unroll
            for (int nt = 0; nt < 4; ++nt) {
                const float p0 = __expf(sc[mt][nt][0] - mn0);
                const float p1 = __expf(sc[mt][nt][1] - mn0);
                const float p2 = __expf(sc[mt][nt][2] - mn1);
                const float p3 = __expf(sc[mt][nt][3] - mn1);
                rs[mt * 2]     += p0 + p1;
                rs[mt * 2 + 1] += p2 + p3;
                pa[mt][nt >> 1][(nt & 1) * 2 + 0] = pack_h2(p0, p1);
                pa[mt][nt >> 1][(nt & 1) * 2 + 1] = pack_h2(p2, p3);
            }
        }
#pragma unroll
        for (int i = 0; i < 4; ++i) {
            rs[i] += __shfl_xor_sync(0xffffffffu, rs[i], 1);
            rs[i] += __shfl_xor_sync(0xffffffffu, rs[i], 2);
            llv[i] = llv[i] * al[i] + rs[i];
        }

#pragma unroll
        for (int mt = 0; mt < 2; ++mt)
#pragma unroll
            for (int nt = 0; nt < 8; ++nt) {
                acc[mt][nt][0] *= al[mt * 2];     acc[mt][nt][1] *= al[mt * 2];
                acc[mt][nt][2] *= al[mt * 2 + 1]; acc[mt][nt][3] *= al[mt * 2 + 1];
            }

        // ---- O += P V over this warp's 32 tokens, full 64 head dims ----
        const uint32_t Vd_u = Vt_u + (uint32_t)(db * FKS_B);
#pragma unroll
        for (int ks = 0; ks < 2; ++ks) {     // two token-16 steps
#pragma unroll
            for (int ntp = 0; ntp < 4; ++ntp) {
                uint32_t b[4];
                ldsm4(b, Vd_u + bk_lane + (uint32_t)(ntp * 16) * KSTRB
                      + (uint32_t)(wc * 32 + ks * 16) * 2);
#pragma unroll
                for (int mt = 0; mt < 2; ++mt) {
                    mma16(acc[mt][ntp * 2],     pa[mt][ks], b);
                    mma16(acc[mt][ntp * 2 + 1], pa[mt][ks], b + 2);
                }
            }
        }
    }

    // ---- epilogue: 2-way split-KV combine across the two column groups ----
    if (ls == 0) {
#pragma unroll
        for (int mt = 0; mt < 2; ++mt) {
            const int r = row0 + mt * 16 + lq;
            cm[wc * 128 + r]     = mm[mt * 2];
            cm[wc * 128 + r + 8] = mm[mt * 2 + 1];
            cl[wc * 128 + r]     = llv[mt * 2];
            cl[wc * 128 + r + 8] = llv[mt * 2 + 1];
        }
    }
    __syncthreads();                     // also fences all loop smem reads

    float sS[4], lt[4];
#pragma unroll
    for (int i = 0; i < 4; ++i) {
        const int row = row0 + (i >> 1) * 16 + (i & 1) * 8 + lq;
        const float mo = cm[(wc ^ 1) * 128 + row];
        const float lo = cl[(wc ^ 1) * 128 + row];
        const float M  = fmaxf(mm[i], mo);
        sS[i] = __expf(mm[i] - M);
        lt[i] = llv[i] * sS[i] + lo * __expf(mo - M);
    }

    if (wc == 1) {                       // publish scaled partial O
#pragma unroll
        for (int mt = 0; mt < 2; ++mt) {
            const int r = row0 + mt * 16 + lq;
#pragma unroll
            for (int nt = 0; nt < 8; ++nt) {
                const int cc = nt * 8 + ls * 2;
                float2 w0, w1;
                w0.x = acc[mt][nt][0] * sS[mt * 2];
                w0.y = acc[mt][nt][1] * sS[mt * 2];
                w1.x = acc[mt][nt][2] * sS[mt * 2 + 1];
                w1.y = acc[mt][nt][3] * sS[mt * 2 + 1];
                *(float2*)(ac + r * 66 + cc)       = w0;
                *(float2*)(ac + (r + 8) * 66 + cc) = w1;
            }
        }
    }
    __syncthreads();

    if (wc == 0) {
        const int b = bh >> 4;
        const int h = bh & 15;
#pragma unroll
        for (int mt = 0; mt < 2; ++mt) {
            const float inv0 = 1.f / lt[mt * 2];
            const float inv1 = 1.f / lt[mt * 2 + 1];
            const int r  = row0 + mt * 16 + lq;
            const int rg = qi * 128 + r;
#pragma unroll
            for (int nt = 0; nt < 8; ++nt) {
                const int cc = nt * 8 + ls * 2;
                const float2 p0 = *(const float2*)(ac + r * 66 + cc);
                const float2 p1 = *(const float2*)(ac + (r + 8) * 66 + cc);
                const int cn = h * HD + cc;
                const uint32_t o0 = pack_h2(
                    (acc[mt][nt][0] * sS[mt * 2] + p0.x) * inv0,
                    (acc[mt][nt][1] * sS[mt * 2] + p0.y) * inv0);
                const uint32_t o1 = pack_h2(
                    (acc[mt][nt][2] * sS[mt * 2 + 1] + p1.x) * inv1,
                    (acc[mt][nt][3] * sS[mt * 2 + 1] + p1.y) * inv1);
                *(uint32_t*)(ctx + (size_t)(b * LL + rg) * DD + cn)     = o0;
                *(uint32_t*)(ctx + (size_t)(b * LL + rg + 8) * DD + cn) = o1;
            }
        }
    }
}

// ---------------------------------------------------------------------------
// Launch
// ---------------------------------------------------------------------------
extern "C" void kernel_launch(void* const* d_in, const int* in_sizes, int n_in,
                              void* d_out, int out_size)
{
    const float* x       = (const float*)d_in[0];
    const float* Wqkv_w  = (const float*)d_in[2];
    const float* Wqkv_b  = (const float*)d_in[3];
    const float* Wout_w  = (const float*)d_in[4];
    const float* Wout_b  = (const float*)d_in[5];

    float* out  = (float*)d_out;
    float* kout = out + BLD;
    float* vout = kout + BLD;

    __half *xr, *wqkv, *wout_r, *qh, *kh, *vh, *ctx;
    float  *qkv;
    cudaGetSymbolAddress((void**)&xr,     g_xr);
    cudaGetSymbolAddress((void**)&wqkv,   g_wqkv);
    cudaGetSymbolAddress((void**)&wout_r, g_wout);
    cudaGetSymbolAddress((void**)&qkv,    g_qkv);
    cudaGetSymbolAddress((void**)&qh,     g_q);
    cudaGetSymbolAddress((void**)&kh,     g_k);
    cudaGetSymbolAddress((void**)&vh,     g_v);
    cudaGetSymbolAddress((void**)&ctx,    g_ctx);

    cudaFuncSetAttribute(gemm_mma,
                         cudaFuncAttributeMaxDynamicSharedMemorySize, GEMM_SMEM);
    cudaFuncSetAttribute(flash_mma,
                         cudaFuncAttributeMaxDynamicSharedMemorySize, FLASH_SMEM);

    round_all<<<(RND_TOTAL4 + 255) / 256, 256>>>(
        (const float4*)x, xr,
        (const float4*)Wqkv_w, wqkv,
        (const float4*)Wout_w, wout_r);

    gemm_mma<<<dim3(QKV_N / 128, ROWS / 128), 256, GEMM_SMEM>>>(
        xr, wqkv, Wqkv_b, qkv, QKV_N, DD);

    rope_scatter<<<(BB * LL * HH * 32) / 256, 256>>>(qkv, qh, kh, vh, kout, vout);

    flash_mma<<<dim3(LL / 128, BB * HH), 256, FLASH_SMEM>>>(qh, kh, vh, ctx);

    gemm_mma<<<dim3(DD / 128, ROWS / 128), 256, GEMM_SMEM>>>(
        ctx, wout_r, Wout_b, out, DD, DD);
}

// round 13
// speedup vs baseline: 1.7768x; 1.0845x over previous
#include <cuda_runtime.h>
#include <cuda_fp16.h>
#include <cstdint>

// Problem shape constants (fixed by the reference).
#define BB 2
#define LL 2048
#define DD 1024
#define HH 16
#define HD 64
#define ROWS (BB*LL)            // 4096
#define QKV_N (3*DD)            // 3072
#define BLD (BB*LL*DD)          // 4194304
#define WQKV_SZ (QKV_N*DD)      // 3145728
#define WOUT_SZ (DD*DD)         // 1048576

// ---------------------------------------------------------------------------
// Scratch (alloc-free rule: __device__ globals)
// ---------------------------------------------------------------------------
__device__ __half g_xr  [BLD];            // x -> fp16
__device__ __half g_wqkv[WQKV_SZ];        // Wqkv -> fp16
__device__ __half g_wout[WOUT_SZ];        // Wout -> fp16
__device__ float  g_qkv [ROWS * QKV_N];   // qkv projection (fp32 accum)
__device__ __half g_q   [BLD];            // q heads, rope'd, scaled, fp16
__device__ __half g_k   [BLD];            // k heads, rope'd, fp16
__device__ __half g_v   [BLD];            // v heads, fp16
__device__ __half g_ctx [BLD];            // attention context, fp16

// ---------------------------------------------------------------------------
// Helpers
// ---------------------------------------------------------------------------
__device__ __forceinline__ uint32_t smem_u32(const void* p) {
    uint32_t a;
    asm("{ .reg .u64 t; cvta.to.shared.u64 t, %1; cvt.u32.u64 %0, t; }"
        : "=r"(a) : "l"(p));
    return a;
}

// m16n8k16 fp16 mma, fp32 accumulate (.row.col)
__device__ __forceinline__ void mma16(float* c, const uint32_t* a, const uint32_t* b) {
    asm volatile(
        "mma.sync.aligned.m16n8k16.row.col.f32.f16.f16.f32 "
        "{%0,%1,%2,%3}, {%4,%5,%6,%7}, {%8,%9}, {%0,%1,%2,%3};"
        : "+f"(c[0]), "+f"(c[1]), "+f"(c[2]), "+f"(c[3])
        : "r"(a[0]), "r"(a[1]), "r"(a[2]), "r"(a[3]), "r"(b[0]), "r"(b[1]));
}

// ldmatrix x4 b16
__device__ __forceinline__ void ldsm4(uint32_t* r, uint32_t addr) {
    asm volatile(
        "ldmatrix.sync.aligned.m8n8.x4.shared.b16 {%0,%1,%2,%3}, [%4];"
        : "=r"(r[0]), "=r"(r[1]), "=r"(r[2]), "=r"(r[3]) : "r"(addr));
}

// ldmatrix x4 b16 transposed (for V: row-major smem -> col-major fragment)
__device__ __forceinline__ void ldsm4t(uint32_t* r, uint32_t addr) {
    asm volatile(
        "ldmatrix.sync.aligned.m8n8.x4.trans.shared.b16 {%0,%1,%2,%3}, [%4];"
        : "=r"(r[0]), "=r"(r[1]), "=r"(r[2]), "=r"(r[3]) : "r"(addr));
}

__device__ __forceinline__ uint32_t pack_h2(float a, float b) {
    __half2 h = __floats2half2_rn(a, b);
    return *(uint32_t*)&h;
}

#define CP16(dst, src) \
    asm volatile("cp.async.cg.shared.global [%0], [%1], 16;" :: "r"(dst), "l"(src))
#define CP_COMMIT() asm volatile("cp.async.commit_group;" ::: "memory")
#define CP_WAIT(n)  asm volatile("cp.async.wait_group %0;" :: "n"(n) : "memory")

// ---------------------------------------------------------------------------
// Fused fp32 -> fp16 conversion of x, Wqkv, Wout
// ---------------------------------------------------------------------------
#define RND_TOTAL4 ((BLD + WQKV_SZ + WOUT_SZ) / 4)

__global__ __launch_bounds__(256) void round_all(
    const float4* __restrict__ x,   __half* __restrict__ xr,
    const float4* __restrict__ wq,  __half* __restrict__ wqr,
    const float4* __restrict__ wo,  __half* __restrict__ wor)
{
    int i = blockIdx.x * 256 + threadIdx.x;
    if (i >= RND_TOTAL4) return;
    const float4* src; __half* dst;
    if (i < BLD/4)                       { src = x;  dst = xr;  }
    else if (i < (BLD + WQKV_SZ)/4)      { src = wq; dst = wqr; i -= BLD/4; }
    else                                 { src = wo; dst = wor; i -= (BLD + WQKV_SZ)/4; }
    float4 v = src[i];
    uint2 o;
    o.x = pack_h2(v.x, v.y);
    o.y = pack_h2(v.z, v.w);
    *(uint2*)(dst + (size_t)i * 4) = o;
}

// ---------------------------------------------------------------------------
// fp16 mma.sync NT GEMM (unchanged): 128x128 CTA tile, BK=32 halves,
// 256 threads, ldmatrix fragments, smem rows padded to 40 halves.
// ---------------------------------------------------------------------------
#define HSTR 40
#define GEMM_TILE_B (128 * HSTR * 2)          // 10240 B per buffer
#define GEMM_SMEM   (4 * GEMM_TILE_B)         // 40960 B

__global__ __launch_bounds__(256) void gemm_mma(
    const __half* __restrict__ A, const __half* __restrict__ B,
    const float* __restrict__ bias, float* __restrict__ C,
    int N, int K)
{
    extern __shared__ char smraw[];
    const uint32_t As_u = smem_u32(smraw);
    const uint32_t Bs_u = As_u + 2 * GEMM_TILE_B;

    const int tid  = threadIdx.x;
    const int lane = tid & 31;
    const int wid  = tid >> 5;
    const int wm   = wid & 1;
    const int wn   = wid >> 1;
    const int lq   = lane >> 2;
    const int ls   = lane & 3;
    const int s    = lane >> 3;
    const int srow = lane & 7;

    const uint32_t a_lane =
        (uint32_t)(wm * 64 + (s & 1) * 8 + srow) * (HSTR * 2) + (s >> 1) * 16;
    const uint32_t b_lane =
        (uint32_t)(wn * 32 + (s >> 1) * 8 + srow) * (HSTR * 2) + (s & 1) * 16;

    const __half* Ab = A + (size_t)(blockIdx.y * 128) * K;
    const __half* Bb = B + (size_t)(blockIdx.x * 128) * K;
    const int KS = K >> 5;

    float acc[4][4][4];
#pragma unroll
    for (int mt = 0; mt < 4; ++mt)
#pragma unroll
        for (int nt = 0; nt < 4; ++nt)
#pragma unroll
            for (int r = 0; r < 4; ++r) acc[mt][nt][r] = 0.f;

#define GEMM_LOAD(ks, db)                                                     \
    {                                                                         \
        const int k0 = (ks) * 32;                                             \
        const uint32_t dA = As_u + (db) * GEMM_TILE_B;                        \
        const uint32_t dB = Bs_u + (db) * GEMM_TILE_B;                        \
        _Pragma("unroll")                                                     \
        for (int i = 0; i < 2; ++i) {                                         \
            const int c   = tid + i * 256;                                    \
            const int row = c >> 2;                                           \
            const int cc  = (c & 3) * 8;                                      \
            const uint32_t off = (uint32_t)row * (HSTR * 2) + cc * 2;         \
            CP16(dA + off, Ab + (size_t)row * K + k0 + cc);                   \
            CP16(dB + off, Bb + (size_t)row * K + k0 + cc);                   \
        }                                                                     \
        CP_COMMIT();                                                          \
    }

    GEMM_LOAD(0, 0);

    for (int ks = 0; ks < KS; ++ks) {
        const int db = ks & 1;
        if (ks + 1 < KS) { GEMM_LOAD(ks + 1, db ^ 1); CP_WAIT(1); }
        else             { CP_WAIT(0); }
        __syncthreads();

        const uint32_t Ad_u = As_u + db * GEMM_TILE_B;
        const uint32_t Bd_u = Bs_u + db * GEMM_TILE_B;

#pragma unroll
        for (int kk = 0; kk < 2; ++kk) {
            uint32_t a[4][4], b[2][4];
#pragma unroll
            for (int mt = 0; mt < 4; ++mt)
                ldsm4(a[mt], Ad_u + a_lane +
                      (uint32_t)(mt * 16 * HSTR * 2 + kk * 32));
#pragma unroll
            for (int ntp = 0; ntp < 2; ++ntp)
                ldsm4(b[ntp], Bd_u + b_lane +
                      (uint32_t)(ntp * 16 * HSTR * 2 + kk * 32));
#pragma unroll
            for (int mt = 0; mt < 4; ++mt)
#pragma unroll
                for (int nt = 0; nt < 4; ++nt)
                    mma16(acc[mt][nt], a[mt], &b[nt >> 1][(nt & 1) * 2]);
        }
        __syncthreads();
    }

    const int row_base = blockIdx.y * 128 + wm * 64;
    const int col_base = blockIdx.x * 128 + wn * 32;
#pragma unroll
    for (int mt = 0; mt < 4; ++mt) {
        const int r0 = row_base + mt * 16 + lq;
#pragma unroll
        for (int nt = 0; nt < 4; ++nt) {
            const int cn = col_base + nt * 8 + ls * 2;
            const float2 bb = *(const float2*)(bias + cn);
            float2 o0, o1;
            o0.x = acc[mt][nt][0] + bb.x;  o0.y = acc[mt][nt][1] + bb.y;
            o1.x = acc[mt][nt][2] + bb.x;  o1.y = acc[mt][nt][3] + bb.y;
            *(float2*)(C + (size_t)r0 * N + cn)       = o0;
            *(float2*)(C + (size_t)(r0 + 8) * N + cn) = o1;
        }
    }
}

// ---------------------------------------------------------------------------
// RoPE + head scatter (unchanged).
// ---------------------------------------------------------------------------
__global__ __launch_bounds__(256) void rope_scatter(
    const float* __restrict__ qkv,
    __half* __restrict__ qh, __half* __restrict__ kh, __half* __restrict__ vh,
    float* __restrict__ kout, float* __restrict__ vout)
{
    const int t = blockIdx.x * blockDim.x + threadIdx.x;
    const int d = t & 31;
    const int h = (t >> 5) & 15;
    const int l = (t >> 9) & 2047;
    const int b = t >> 20;

    const float* base = qkv + (size_t)(b * LL + l) * QKV_N;

    const float inv = __expf(-(float)d * (9.210340371976184f / 32.f));
    const float ang = (float)l * inv;
    float sn, cs;
    sincosf(ang, &sn, &cs);

    const size_t ob = ((size_t)((b * HH + h) * LL + l)) * HD;

    const float q1 = base[h*HD + d], q2 = base[h*HD + d + 32];
    qh[ob + d]      = __float2half_rn((q1 * cs - q2 * sn) * 0.125f);
    qh[ob + d + 32] = __float2half_rn((q1 * sn + q2 * cs) * 0.125f);

    const float k1 = base[DD + h*HD + d], k2 = base[DD + h*HD + d + 32];
    const float kr1 = k1 * cs - k2 * sn;
    const float kr2 = k1 * sn + k2 * cs;
    kout[ob + d]      = kr1;
    kout[ob + d + 32] = kr2;
    kh[ob + d]        = __float2half_rn(kr1);
    kh[ob + d + 32]   = __float2half_rn(kr2);

    const float v1 = base[2*DD + h*HD + d], v2 = base[2*DD + h*HD + d + 32];
    vout[ob + d]      = v1;
    vout[ob + d + 32] = v2;
    vh[ob + d]        = __float2half_rn(v1);
    vh[ob + d + 32]   = __float2half_rn(v2);
}

// ---------------------------------------------------------------------------
// Flash attention v10 (fp16, register-P, ldmatrix.trans V):
// Br=128, Bc=64, 256 threads (8 warps = 4 row-groups x 2 col-groups).
// V stored ROW-major (cp.async, same loader as K); PV B-fragments loaded via
// ldmatrix.trans -- no LDG->STS transpose path at all.
// smem bytes: Ks[2][64*72h]=18432 | Vs[2][64*72h]=18432 | cm[2][128]f=1024 |
//             cl[2][128]f=1024    total 38912.
// Epilogue 'ac' (128 x 66 fp32 = 33792 B) aliases Ks+Vs (dead by then).
// ---------------------------------------------------------------------------
#define KSTRB 144                     // 72 halves per row
#define FKS_B  (64 * KSTRB)           // 9216 per K/V buffer
#define FVT_O  (2 * FKS_B)            // 18432
#define FCM_O  (FVT_O + 2 * FKS_B)    // 36864
#define FCL_O  (FCM_O + 1024)         // 37888
#define FLASH_SMEM (FCL_O + 1024)     // 38912 B

__global__ __launch_bounds__(256) void flash_mma(
    const __half* __restrict__ Q, const __half* __restrict__ K,
    const __half* __restrict__ V, __half* __restrict__ ctx)
{
    extern __shared__ char smraw[];
    float*  cm = (float*)(smraw + FCM_O);   // [2][128]
    float*  cl = (float*)(smraw + FCL_O);   // [2][128]
    float*  ac = (float*)smraw;             // epilogue alias, stride 66
    const uint32_t Ks_u = smem_u32(smraw);
    const uint32_t Vs_u = Ks_u + FVT_O;

    const int qi   = gridDim.x - 1 - blockIdx.x;   // heavy tiles first
    const int bh   = blockIdx.y;
    const int tid  = threadIdx.x;
    const int lane = tid & 31;
    const int wid  = tid >> 5;           // 0..7
    const int wr   = wid & 3;            // row group (4 x 32 rows)
    const int wc   = wid >> 2;           // col group (2 x 32 tokens)
    const int lq   = lane >> 2;
    const int ls   = lane & 3;
    const int s    = lane >> 3;
    const int srow = lane & 7;
    const int row0 = wr * 32;

    // ldmatrix lane offsets (bytes)
    // K B-frag (non-trans): (s>>1)->+8 token-rows, (s&1)->k-half (16B)
    const uint32_t bk_lane =
        (uint32_t)((s >> 1) * 8 + srow) * KSTRB + (s & 1) * 16;
    // V B-frag (trans): (s&1)->+8 token-rows, (s>>1)->+8 dims (16B)
    const uint32_t bv_lane =
        (uint32_t)((s & 1) * 8 + srow) * KSTRB + (s >> 1) * 16;

    const __half* Qb = Q + ((size_t)bh * LL + qi * 128) * HD;
    const __half* Kb = K + (size_t)bh * LL * HD;
    const __half* Vb = V + (size_t)bh * LL * HD;

    // tile loader (64 tokens x 64 halves; 2 cp.async per thread)
#define FL_LOAD_T(dst_u, src)                                                 \
    {                                                                         \
        _Pragma("unroll")                                                     \
        for (int i = 0; i < 2; ++i) {                                         \
            const int c   = tid + i * 256;                                    \
            const int row = c >> 3;                                           \
            const int cc  = (c & 7) * 8;                                      \
            CP16((dst_u) + (uint32_t)row * KSTRB + cc * 2,                    \
                 (src) + (size_t)row * HD + cc);                              \
        }                                                                     \
    }

    // prologue: K0 + V0 in one cp.async group
    FL_LOAD_T(Ks_u, Kb);
    FL_LOAD_T(Vs_u, Vb);
    CP_COMMIT();

    // Q register-resident fragments: 4 k16-steps x 2 row-tiles x 4 regs
    uint32_t qf[4][2][4];
#pragma unroll
    for (int ks = 0; ks < 4; ++ks) {
#pragma unroll
        for (int mt = 0; mt < 2; ++mt) {
            const int r = row0 + mt * 16 + lq;
            const __half* q0 = Qb + (size_t)r * HD + ks * 16;
            const __half* q1 = Qb + (size_t)(r + 8) * HD + ks * 16;
            qf[ks][mt][0] = *(const uint32_t*)(q0 + 2 * ls);
            qf[ks][mt][1] = *(const uint32_t*)(q1 + 2 * ls);
            qf[ks][mt][2] = *(const uint32_t*)(q0 + 8 + 2 * ls);
            qf[ks][mt][3] = *(const uint32_t*)(q1 + 8 + 2 * ls);
        }
    }

    float acc[2][8][4];
#pragma unroll
    for (int mt = 0; mt < 2; ++mt)
#pragma unroll
        for (int nt = 0; nt < 8; ++nt)
#pragma unroll
            for (int r = 0; r < 4; ++r) acc[mt][nt][r] = 0.f;
    float mm[4] = {-1e30f, -1e30f, -1e30f, -1e30f};
    float llv[4] = {0.f, 0.f, 0.f, 0.f};

    const int jtmax = 2 * qi + 1;

    for (int jt = 0; jt <= jtmax; ++jt) {
        const int db = jt & 1;
        CP_WAIT(0);
        __syncthreads();                 // K_jt/V_jt visible; db^1 reads done

        if (jt < jtmax) {
            FL_LOAD_T(Ks_u + (uint32_t)((db ^ 1) * FKS_B),
                      Kb + (size_t)(jt + 1) * 64 * HD);
            FL_LOAD_T(Vs_u + (uint32_t)((db ^ 1) * FKS_B),
                      Vb + (size_t)(jt + 1) * 64 * HD);
            CP_COMMIT();
        }

        // ---- S = Q K^T on this warp's 32 tokens ----
        float sc[2][4][4];
#pragma unroll
        for (int mt = 0; mt < 2; ++mt)
#pragma unroll
            for (int nt = 0; nt < 4; ++nt)
#pragma unroll
                for (int r = 0; r < 4; ++r) sc[mt][nt][r] = 0.f;

        const uint32_t Kd_u = Ks_u + (uint32_t)(db * FKS_B)
                            + (uint32_t)(wc * 32) * KSTRB + bk_lane;
#pragma unroll
        for (int ks = 0; ks < 4; ++ks) {
#pragma unroll
            for (int ntp = 0; ntp < 2; ++ntp) {
                uint32_t b[4];
                ldsm4(b, Kd_u + (uint32_t)(ntp * 16) * KSTRB + ks * 32);
#pragma unroll
                for (int mt = 0; mt < 2; ++mt) {
                    mma16(sc[mt][ntp * 2],     qf[ks][mt], b);
                    mma16(sc[mt][ntp * 2 + 1], qf[ks][mt], b + 2);
                }
            }
        }

        // ---- causal mask (last two tiles) ----
        if (jt >= 2 * qi) {
            const int cbase = jt * 64 + wc * 32;
#pragma unroll
            for (int mt = 0; mt < 2; ++mt) {
                const int rg0 = qi * 128 + row0 + mt * 16 + lq;
#pragma unroll
                for (int nt = 0; nt < 4; ++nt) {
                    const int cg = cbase + nt * 8 + ls * 2;
                    if (cg > rg0)         sc[mt][nt][0] += -1000000000.0f;
                    if (cg + 1 > rg0)     sc[mt][nt][1] += -1000000000.0f;
                    if (cg > rg0 + 8)     sc[mt][nt][2] += -1000000000.0f;
                    if (cg + 1 > rg0 + 8) sc[mt][nt][3] += -1000000000.0f;
                }
            }
        }

        // ---- row max per row-pair group (quad shfl) ----
        float mx[4];
#pragma unroll
        for (int mt = 0; mt < 2; ++mt) {
            float a0 = sc[mt][0][0], a1 = sc[mt][0][2];
#pragma unroll
            for (int nt = 0; nt < 4; ++nt) {
                a0 = fmaxf(a0, fmaxf(sc[mt][nt][0], sc[mt][nt][1]));
                a1 = fmaxf(a1, fmaxf(sc[mt][nt][2], sc[mt][nt][3]));
            }
            mx[mt * 2]     = a0;
            mx[mt * 2 + 1] = a1;
        }
#pragma unroll
        for (int i = 0; i < 4; ++i) {
            mx[i] = fmaxf(mx[i], __shfl_xor_sync(0xffffffffu, mx[i], 1));
            mx[i] = fmaxf(mx[i], __shfl_xor_sync(0xffffffffu, mx[i], 2));
        }

        float al[4];
#pragma unroll
        for (int i = 0; i < 4; ++i) {
            const float mn = fmaxf(mm[i], mx[i]);
            al[i] = __expf(mm[i] - mn);
            mm[i] = mn;
        }

        // ---- P = exp(S - m): pack straight into PV A-fragments ----
        uint32_t pa[2][2][4];
        float rs[4] = {0.f, 0.f, 0.f, 0.f};
#pragma unroll
        for (int mt = 0; mt < 2; ++mt) {
            const float mn0 = mm[mt * 2], mn1 = mm[mt * 2 + 1];
#pragma unroll
            for (int nt = 0; nt < 4; ++nt) {
                const float p0 = __expf(sc[mt][nt][0] - mn0);
                const float p1 = __expf(sc[mt][nt][1] - mn0);
                const float p2 = __expf(sc[mt][nt][2] - mn1);
                const float p3 = __expf(sc[mt][nt][3] - mn1);
                rs[mt * 2]     += p0 + p1;
                rs[mt * 2 + 1] += p2 + p3;
                pa[mt][nt >> 1][(nt & 1) * 2 + 0] = pack_h2(p0, p1);
                pa[mt][nt >> 1][(nt & 1) * 2 + 1] = pack_h2(p2, p3);
            }
        }
#pragma unroll
        for (int i = 0; i < 4; ++i) {
            rs[i] += __shfl_xor_sync(0xffffffffu, rs[i], 1);
            rs[i] += __shfl_xor_sync(0xffffffffu, rs[i], 2);
            llv[i] = llv[i] * al[i] + rs[i];
        }

#pragma unroll
        for (int mt = 0; mt < 2; ++mt)
#pragma unroll
            for (int nt = 0; nt < 8; ++nt) {
                acc[mt][nt][0] *= al[mt * 2];     acc[mt][nt][1] *= al[mt * 2];
                acc[mt][nt][2] *= al[mt * 2 + 1]; acc[mt][nt][3] *= al[mt * 2 + 1];
            }

        // ---- O += P V: B-frags via ldmatrix.trans from row-major V ----
        const uint32_t Vd_u = Vs_u + (uint32_t)(db * FKS_B) + bv_lane;
#pragma unroll
        for (int ks = 0; ks < 2; ++ks) {     // two token-16 steps
            const uint32_t vtok_off =
                (uint32_t)(wc * 32 + ks * 16) * KSTRB;
#pragma unroll
            for (int ntp = 0; ntp < 4; ++ntp) {
                uint32_t b[4];
                ldsm4t(b, Vd_u + vtok_off + (uint32_t)(ntp * 16) * 2);
#pragma unroll
                for (int mt = 0; mt < 2; ++mt) {
                    mma16(acc[mt][ntp * 2],     pa[mt][ks], b);
                    mma16(acc[mt][ntp * 2 + 1], pa[mt][ks], b + 2);
                }
            }
        }
    }

    // ---- epilogue: 2-way split-KV combine across the two column groups ----
    if (ls == 0) {
#pragma unroll
        for (int mt = 0; mt < 2; ++mt) {
            const int r = row0 + mt * 16 + lq;
            cm[wc * 128 + r]     = mm[mt * 2];
            cm[wc * 128 + r + 8] = mm[mt * 2 + 1];
            cl[wc * 128 + r]     = llv[mt * 2];
            cl[wc * 128 + r + 8] = llv[mt * 2 + 1];
        }
    }
    __syncthreads();                     // also fences all loop smem reads

    float sS[4], lt[4];
#pragma unroll
    for (int i = 0; i < 4; ++i) {
        const int row = row0 + (i >> 1) * 16 + (i & 1) * 8 + lq;
        const float mo = cm[(wc ^ 1) * 128 + row];
        const float lo = cl[(wc ^ 1) * 128 + row];
        const float M  = fmaxf(mm[i], mo);
        sS[i] = __expf(mm[i] - M);
        lt[i] = llv[i] * sS[i] + lo * __expf(mo - M);
    }

    if (wc == 1) {                       // publish scaled partial O
#pragma unroll
        for (int mt = 0; mt < 2; ++mt) {
            const int r = row0 + mt * 16 + lq;
#pragma unroll
            for (int nt = 0; nt < 8; ++nt) {
                const int cc = nt * 8 + ls * 2;
                float2 w0, w1;
                w0.x = acc[mt][nt][0] * sS[mt * 2];
                w0.y = acc[mt][nt][1] * sS[mt * 2];
                w1.x = acc[mt][nt][2] * sS[mt * 2 + 1];
                w1.y = acc[mt][nt][3] * sS[mt * 2 + 1];
                *(float2*)(ac + r * 66 + cc)       = w0;
                *(float2*)(ac + (r + 8) * 66 + cc) = w1;
            }
        }
    }
    __syncthreads();

    if (wc == 0) {
        const int b = bh >> 4;
        const int h = bh & 15;
#pragma unroll
        for (int mt = 0; mt < 2; ++mt) {
            const float inv0 = 1.f / lt[mt * 2];
            const float inv1 = 1.f / lt[mt * 2 + 1];
            const int r  = row0 + mt * 16 + lq;
            const int rg = qi * 128 + r;
#pragma unroll
            for (int nt = 0; nt < 8; ++nt) {
                const int cc = nt * 8 + ls * 2;
                const float2 p0 = *(const float2*)(ac + r * 66 + cc);
                const float2 p1 = *(const float2*)(ac + (r + 8) * 66 + cc);
                const int cn = h * HD + cc;
                const uint32_t o0 = pack_h2(
                    (acc[mt][nt][0] * sS[mt * 2] + p0.x) * inv0,
                    (acc[mt][nt][1] * sS[mt * 2] + p0.y) * inv0);
                const uint32_t o1 = pack_h2(
                    (acc[mt][nt][2] * sS[mt * 2 + 1] + p1.x) * inv1,
                    (acc[mt][nt][3] * sS[mt * 2 + 1] + p1.y) * inv1);
                *(uint32_t*)(ctx + (size_t)(b * LL + rg) * DD + cn)     = o0;
                *(uint32_t*)(ctx + (size_t)(b * LL + rg + 8) * DD + cn) = o1;
            }
        }
    }
}

// ---------------------------------------------------------------------------
// Launch
// ---------------------------------------------------------------------------
extern "C" void kernel_launch(void* const* d_in, const int* in_sizes, int n_in,
                              void* d_out, int out_size)
{
    const float* x       = (const float*)d_in[0];
    const float* Wqkv_w  = (const float*)d_in[2];
    const float* Wqkv_b  = (const float*)d_in[3];
    const float* Wout_w  = (const float*)d_in[4];
    const float* Wout_b  = (const float*)d_in[5];

    float* out  = (float*)d_out;
    float* kout = out + BLD;
    float* vout = kout + BLD;

    __half *xr, *wqkv, *wout_r, *qh, *kh, *vh, *ctx;
    float  *qkv;
    cudaGetSymbolAddress((void**)&xr,     g_xr);
    cudaGetSymbolAddress((void**)&wqkv,   g_wqkv);
    cudaGetSymbolAddress((void**)&wout_r, g_wout);
    cudaGetSymbolAddress((void**)&qkv,    g_qkv);
    cudaGetSymbolAddress((void**)&qh,     g_q);
    cudaGetSymbolAddress((void**)&kh,     g_k);
    cudaGetSymbolAddress((void**)&vh,     g_v);
    cudaGetSymbolAddress((void**)&ctx,    g_ctx);

    cudaFuncSetAttribute(gemm_mma,
                         cudaFuncAttributeMaxDynamicSharedMemorySize, GEMM_SMEM);
    cudaFuncSetAttribute(flash_mma,
                         cudaFuncAttributeMaxDynamicSharedMemorySize, FLASH_SMEM);

    round_all<<<(RND_TOTAL4 + 255) / 256, 256>>>(
        (const float4*)x, xr,
        (const float4*)Wqkv_w, wqkv,
        (const float4*)Wout_w, wout_r);

    gemm_mma<<<dim3(QKV_N / 128, ROWS / 128), 256, GEMM_SMEM>>>(
        xr, wqkv, Wqkv_b, qkv, QKV_N, DD);

    rope_scatter<<<(BB * LL * HH * 32) / 256, 256>>>(qkv, qh, kh, vh, kout, vout);

    flash_mma<<<dim3(LL / 128, BB * HH), 256, FLASH_SMEM>>>(qh, kh, vh, ctx);

    gemm_mma<<<dim3(DD / 128, ROWS / 128), 256, GEMM_SMEM>>>(
        ctx, wout_r, Wout_b, out, DD, DD);
}